// round 14
// baseline (speedup 1.0000x reference)
#include <cuda_runtime.h>
#include <math.h>
#include <stdint.h>

#define BB 8
#define LL 128
#define DD 512
#define EE 64
#define HH 8
#define BL (BB*LL)   // 1024

typedef unsigned long long ull;

__device__ __forceinline__ void fma2(ull &acc, ull a, ull b) {
    asm("fma.rn.f32x2 %0, %1, %2, %0;" : "+l"(acc) : "l"(a), "l"(b));
}
__device__ __forceinline__ void add2(ull &a, ull b) {
    asm("add.rn.f32x2 %0, %0, %1;" : "+l"(a) : "l"(b));
}
__device__ __forceinline__ ull pack2(float x, float y) {
    ull r; asm("mov.b64 %0, {%1,%2};" : "=l"(r) : "f"(x), "f"(y)); return r;
}
__device__ __forceinline__ void unpack2(ull v, float &x, float &y) {
    asm("mov.b64 {%0,%1}, %2;" : "=f"(x), "=f"(y) : "l"(v));
}
__device__ __forceinline__ float fsum2(ull v) {
    float x, y; unpack2(v, x, y); return x + y;
}

// cp.async helpers
__device__ __forceinline__ uint32_t smem_u32(const void* p) {
    uint32_t a;
    asm("{ .reg .u64 t; cvta.to.shared.u64 t, %1; cvt.u32.u64 %0, t; }" : "=r"(a) : "l"(p));
    return a;
}
__device__ __forceinline__ void cp16(uint32_t d, const void* s) {
    asm volatile("cp.async.ca.shared.global [%0], [%1], 16;" :: "r"(d), "l"(s));
}
__device__ __forceinline__ void cp_commit() {
    asm volatile("cp.async.commit_group;" ::: "memory");
}
template<int N> __device__ __forceinline__ void cp_wait() {
    asm volatile("cp.async.wait_group %0;" :: "n"(N) : "memory");
}

// Scratch — split-K accumulation targets live in ONE array (single memset node)
__device__ float dACC[4 * BL * DD];      // [dQ | dKV | dATTN | dFFN]
#define dQ_P    (dACC)
#define dKV_P   (dACC + (size_t)BL * DD)
#define dATTN_P (dACC + (size_t)2 * BL * DD)
#define dFFN_P  (dACC + (size_t)3 * BL * DD)

__device__ float dG[BL*HH*EE];           // [bq][h][e]
__device__ float dS1[BB*HH*LL*LL];       // [bh][q][k]
__device__ float dALPHA[BB*HH*LL*LL];    // [bh][q][k]
__device__ float dWsum[BB*HH*LL*EE];     // [bh][q][e]

// ---------------------------------------------------------------------------
// Split-K cp.async f32x2 GEMM: 64x64 tile, 128 threads, 2-stage (R12 proven).
// ---------------------------------------------------------------------------
__global__ __launch_bounds__(128) void gemm_ca(
    const float* __restrict__ A,
    const float* __restrict__ B0, float* __restrict__ C0,
    const float* __restrict__ B1, float* __restrict__ C1,
    const float* __restrict__ bias, int lda, int K2, int N, int nsplit)
{
    __shared__ float As[2][64*36];
    __shared__ float Bs[2][32*64];

    const int mat = blockIdx.z / nsplit;
    const int sp  = blockIdx.z % nsplit;
    const float* Bm = mat ? B1 : B0;
    float*       Cm = mat ? C1 : C0;
    const int kbase = sp * K2;

    const int t  = threadIdx.x;
    const int tx = t & 15, ty = t >> 4;
    const int m0 = blockIdx.y * 64, n0 = blockIdx.x * 64;

    const uint32_t asb = smem_u32(&As[0][0]);
    const uint32_t bsb = smem_u32(&Bs[0][0]);

    ull acc[8][2] = {};

    #define ISSUE_TILE(buf, k0) do {                                            \
        _Pragma("unroll")                                                       \
        for (int r = 0; r < 4; r++) {                                           \
            int idx = t + r * 128;                                              \
            int m = idx >> 3, k4 = (idx & 7) << 2;                              \
            cp16(asb + (buf) * 9216u + (uint32_t)(m * 36 + k4) * 4u,            \
                 A + (size_t)(m0 + m) * lda + (k0) + k4);                       \
        }                                                                       \
        _Pragma("unroll")                                                       \
        for (int r = 0; r < 4; r++) {                                           \
            int idx = t + r * 128;                                              \
            int kk = idx >> 4, n4 = (idx & 15) << 2;                            \
            cp16(bsb + (buf) * 8192u + (uint32_t)(kk * 64 + n4) * 4u,           \
                 Bm + (size_t)((k0) + kk) * N + n0 + n4);                       \
        }                                                                       \
        cp_commit();                                                            \
    } while (0)

    ISSUE_TILE(0, kbase);

    const int NT = K2 / 32;
    int buf = 0;
    for (int kt = 0; kt < NT; kt++) {
        if (kt + 1 < NT) { ISSUE_TILE(buf ^ 1, kbase + (kt + 1) * 32); cp_wait<1>(); }
        else             { cp_wait<0>(); }
        __syncthreads();

        #pragma unroll 4
        for (int kk = 0; kk < 32; kk += 2) {
            ull bp00 = *(const ull*)&Bs[buf][kk * 64 + tx * 2];
            ull bp01 = *(const ull*)&Bs[buf][kk * 64 + tx * 2 + 32];
            ull bp10 = *(const ull*)&Bs[buf][(kk + 1) * 64 + tx * 2];
            ull bp11 = *(const ull*)&Bs[buf][(kk + 1) * 64 + tx * 2 + 32];
            #pragma unroll
            for (int i = 0; i < 8; i++) {
                float2 af = *(const float2*)&As[buf][(ty * 8 + i) * 36 + kk];
                ull ad0 = pack2(af.x, af.x);
                ull ad1 = pack2(af.y, af.y);
                fma2(acc[i][0], ad0, bp00);
                fma2(acc[i][1], ad0, bp01);
                fma2(acc[i][0], ad1, bp10);
                fma2(acc[i][1], ad1, bp11);
            }
        }
        __syncthreads();
        buf ^= 1;
    }
    #undef ISSUE_TILE

    #pragma unroll
    for (int i = 0; i < 8; i++) {
        int m = m0 + ty * 8 + i;
        float x0, x1, y0, y1;
        unpack2(acc[i][0], x0, x1);
        unpack2(acc[i][1], y0, y1);
        int nA = n0 + tx * 2, nB = nA + 32;
        if (bias && sp == 0) {
            x0 += bias[nA]; x1 += bias[nA + 1];
            y0 += bias[nB]; y1 += bias[nB + 1];
        }
        float* crow = Cm + (size_t)m * N;
        atomicAdd(crow + nA,     x0);
        atomicAdd(crow + nA + 1, x1);
        atomicAdd(crow + nB,     y0);
        atomicAdd(crow + nB + 1, y1);
    }
}

// ---------------------------------------------------------------------------
// attn split-K cp.async GEMM (R12 measured best): 64x64 tiles, 128 threads,
// grid (64, 2, 2); K=192 -> 2x96. atomicAdd into zeroed dATTN.
// ---------------------------------------------------------------------------
__global__ __launch_bounds__(128) void attn_ca(const float* __restrict__ We)
{
    __shared__ float As[2][64*36];
    __shared__ float Bs[2][32*64];

    const int bh = blockIdx.x, mh = blockIdx.y, sp = blockIdx.z;
    const int b  = bh >> 3, h = bh & 7;
    const int t  = threadIdx.x;
    const int tx = t & 15, ty = t >> 4;
    const int kbase = sp * 96;

    const uint32_t asb = smem_u32(&As[0][0]);
    const uint32_t bsb = smem_u32(&Bs[0][0]);

    ull acc[8][2] = {};

    #define ISSUE_ATTN(buf, k0) do {                                            \
        _Pragma("unroll")                                                       \
        for (int r = 0; r < 4; r++) {                                           \
            int idx = t + r * 128;                                              \
            int m = idx >> 3, k4 = (idx & 7) << 2;                              \
            size_t row = (size_t)bh * LL + mh * 64 + m;                         \
            const float* src = ((k0) < 128)                                     \
                ? (dALPHA + row * LL + (k0) + k4)                               \
                : (dWsum  + row * EE + ((k0) - 128) + k4);                      \
            cp16(asb + (buf) * 9216u + (uint32_t)(m * 36 + k4) * 4u, src);      \
        }                                                                       \
        _Pragma("unroll")                                                       \
        for (int r = 0; r < 4; r++) {                                           \
            int idx = t + r * 128;                                              \
            int kk = idx >> 4, n4 = (idx & 15) << 2;                            \
            int kg = (k0) + kk;                                                 \
            const float* src = (kg < 128)                                       \
                ? (dKV_P + (size_t)(b * LL + kg) * DD + h * 64 + n4)            \
                : (We    + (size_t)(kg - 128) * DD + h * 64 + n4);              \
            cp16(bsb + (buf) * 8192u + (uint32_t)(kk * 64 + n4) * 4u, src);     \
        }                                                                       \
        cp_commit();                                                            \
    } while (0)

    ISSUE_ATTN(0, kbase);

    const int NT = 3;   // 96 per split
    int buf = 0;
    for (int kt = 0; kt < NT; kt++) {
        if (kt + 1 < NT) { ISSUE_ATTN(buf ^ 1, kbase + (kt + 1) * 32); cp_wait<1>(); }
        else             { cp_wait<0>(); }
        __syncthreads();

        #pragma unroll 4
        for (int kk = 0; kk < 32; kk += 2) {
            ull bp00 = *(const ull*)&Bs[buf][kk * 64 + tx * 2];
            ull bp01 = *(const ull*)&Bs[buf][kk * 64 + tx * 2 + 32];
            ull bp10 = *(const ull*)&Bs[buf][(kk + 1) * 64 + tx * 2];
            ull bp11 = *(const ull*)&Bs[buf][(kk + 1) * 64 + tx * 2 + 32];
            #pragma unroll
            for (int i = 0; i < 8; i++) {
                float2 af = *(const float2*)&As[buf][(ty * 8 + i) * 36 + kk];
                ull ad0 = pack2(af.x, af.x);
                ull ad1 = pack2(af.y, af.y);
                fma2(acc[i][0], ad0, bp00);
                fma2(acc[i][1], ad0, bp01);
                fma2(acc[i][0], ad1, bp10);
                fma2(acc[i][1], ad1, bp11);
            }
        }
        __syncthreads();
        buf ^= 1;
    }
    #undef ISSUE_ATTN

    #pragma unroll
    for (int i = 0; i < 8; i++) {
        int m = mh * 64 + ty * 8 + i;
        float* crow = dATTN_P + ((size_t)(b * LL) + m) * DD + h * 64;
        float x0, x1, y0, y1;
        unpack2(acc[i][0], x0, x1);
        unpack2(acc[i][1], y0, y1);
        atomicAdd(crow + tx * 2,      x0);
        atomicAdd(crow + tx * 2 + 1,  x1);
        atomicAdd(crow + tx * 2 + 32, y0);
        atomicAdd(crow + tx * 2 + 33, y1);
    }
}

// ---------------------------------------------------------------------------
// Merged s1 + g kernel (proven): 256 blocks x 256 threads.
// ---------------------------------------------------------------------------
__global__ __launch_bounds__(256) void s1g_kernel(const float* __restrict__ We)
{
    __shared__ float pool[8320];

    const int bx = blockIdx.x;
    const int t  = threadIdx.x;
    const int tx = t & 15, ty = t >> 4;

    if (bx < 128) {
        float* Qs = pool;            // [64][34]
        float* Ks = pool + 2176;     // [128][34]
        const int bh = bx >> 1, mh = bx & 1;
        const int b  = bh >> 3, h = bh & 7;

        ull acc[4][8] = {};

        for (int c0 = 0; c0 < 64; c0 += 32) {
            #pragma unroll
            for (int r = 0; r < 2; r++) {
                int idx = t + r * 256;
                int m   = idx >> 3;
                int c4  = (idx & 7) << 2;
                float4 v = *(const float4*)(dQ_P + (size_t)(b * LL + mh * 64 + m) * DD + h * 64 + c0 + c4);
                *(float2*)(Qs + m * 34 + c4)     = make_float2(v.x, v.y);
                *(float2*)(Qs + m * 34 + c4 + 2) = make_float2(v.z, v.w);
            }
            #pragma unroll
            for (int r = 0; r < 4; r++) {
                int idx = t + r * 256;
                int n   = idx >> 3;
                int c4  = (idx & 7) << 2;
                float4 v = *(const float4*)(dKV_P + (size_t)(b * LL + n) * DD + h * 64 + c0 + c4);
                *(float2*)(Ks + n * 34 + c4)     = make_float2(v.x, v.y);
                *(float2*)(Ks + n * 34 + c4 + 2) = make_float2(v.z, v.w);
            }
            __syncthreads();

            #pragma unroll
            for (int cc = 0; cc < 32; cc += 2) {
                ull a[4], b2[8];
                #pragma unroll
                for (int i = 0; i < 4; i++) a[i]  = *(const ull*)(Qs + (ty * 4 + i) * 34 + cc);
                #pragma unroll
                for (int j = 0; j < 8; j++) b2[j] = *(const ull*)(Ks + (tx + 16 * j) * 34 + cc);
                #pragma unroll
                for (int i = 0; i < 4; i++)
                    #pragma unroll
                    for (int j = 0; j < 8; j++)
                        fma2(acc[i][j], a[i], b2[j]);
            }
            __syncthreads();
        }

        #pragma unroll
        for (int i = 0; i < 4; i++) {
            int m = mh * 64 + ty * 4 + i;
            #pragma unroll
            for (int j = 0; j < 8; j++)
                dS1[((size_t)bh * LL + m) * LL + tx + 16 * j] = fsum2(acc[i][j]);
        }
    } else {
        float* Qs = pool;            // [64][65]
        float* Ws = pool + 4160;     // [64][65]
        const int idx0 = bx - 128;
        const int r0 = (idx0 >> 3) * 64;
        const int h  = idx0 & 7;

        #pragma unroll
        for (int r = 0; r < 4; r++) {
            int idx = t + r * 256;
            int m   = idx >> 4;
            int c4  = (idx & 15) << 2;
            float4 q = *(const float4*)(dQ_P + (size_t)(r0 + m) * DD + h * 64 + c4);
            Qs[m * 65 + c4 + 0] = q.x; Qs[m * 65 + c4 + 1] = q.y;
            Qs[m * 65 + c4 + 2] = q.z; Qs[m * 65 + c4 + 3] = q.w;
            float4 w = *(const float4*)(We + (size_t)m * DD + h * 64 + c4);
            Ws[m * 65 + c4 + 0] = w.x; Ws[m * 65 + c4 + 1] = w.y;
            Ws[m * 65 + c4 + 2] = w.z; Ws[m * 65 + c4 + 3] = w.w;
        }
        __syncthreads();

        float acc[4][4] = {};
        #pragma unroll
        for (int c = 0; c < 64; c++) {
            float a[4], b[4];
            #pragma unroll
            for (int i = 0; i < 4; i++) a[i] = Qs[(ty + 16 * i) * 65 + c];
            #pragma unroll
            for (int j = 0; j < 4; j++) b[j] = Ws[(tx + 16 * j) * 65 + c];
            #pragma unroll
            for (int i = 0; i < 4; i++)
                #pragma unroll
                for (int j = 0; j < 4; j++)
                    acc[i][j] += a[i] * b[j];
        }

        #pragma unroll
        for (int i = 0; i < 4; i++) {
            int m = r0 + ty + 16 * i;
            #pragma unroll
            for (int j = 0; j < 4; j++)
                dG[((size_t)m * HH + h) * EE + tx + 16 * j] = acc[i][j];
        }
    }
}

// ---------------------------------------------------------------------------
// Softmax v7: PERSISTENT + double-buffered cp.async across q.
// 256 blocks x 256 threads, each block owns 4 q's; while computing q_i the
// whole stream for q_{i+1} (es, S1 slab, dG row, adj) lands in buffer ^1.
// es stored XOR-swizzled (stride 64, float4 col p = c4 ^ (k&15)):
//   phase A row reads 2-way instead of 4-way conflicted; phase C stays free.
// Dynamic smem 85120 B -> 2 blocks/SM.
// ---------------------------------------------------------------------------
__global__ __launch_bounds__(256) void softmax7(
    const float* __restrict__ eptr, const int* __restrict__ adj)
{
    extern __shared__ char smdyn[];
    float* es   = (float*)(smdyn);            // 2 x 128 x 64     (65536 B)
    float* sS1  = (float*)(smdyn + 65536);    // 2 x 8 x 128      (8192 B)
    float* gRaw = (float*)(smdyn + 73728);    // 2 x 512          (4096 B)
    int*   adjs = (int*)  (smdyn + 77824);    // 2 x 128          (1024 B)
    float* gT   = (float*)(smdyn + 78848);    // 512 [j][h]       (2048 B)
    float* aT   = (float*)(smdyn + 80896);    // 1024             (4096 B)
    float* redS = (float*)(smdyn + 84992);    // 32               (128 B)

    const uint32_t base = smem_u32(smdyn);
    const int bx = blockIdx.x;
    const int t  = threadIdx.x;
    const int lane = t & 31, warp = t >> 5;

    #define SMX_ISSUE(bq, bf) do {                                              \
        const int b_ = (bq) >> 7, q_ = (bq) & 127;                              \
        const float* erow_ = eptr + (size_t)(bq) * (LL * EE);                   \
        _Pragma("unroll")                                                       \
        for (int r = 0; r < 8; r++) {                                           \
            int idx = t + r * 256;                                              \
            int k_ = idx >> 4, c4_ = idx & 15;                                  \
            int p_ = c4_ ^ (k_ & 15);                                           \
            cp16(base + (uint32_t)(bf) * 32768u + (uint32_t)(k_ * 256 + p_ * 16), \
                 erow_ + k_ * EE + c4_ * 4);                                    \
        }                                                                       \
        {                                                                       \
            int h_ = t >> 5, k4_ = (t & 31) << 2;                               \
            cp16(base + 65536u + (uint32_t)(bf) * 4096u + (uint32_t)(h_ * 512 + k4_ * 4), \
                 dS1 + (((size_t)(b_ * HH + h_)) * LL + q_) * LL + k4_);        \
        }                                                                       \
        if (t < 128) cp16(base + 73728u + (uint32_t)(bf) * 2048u + (uint32_t)t * 16u, \
                          dG + (size_t)(bq) * 512 + t * 4);                     \
        if (t < 32)  cp16(base + 77824u + (uint32_t)(bf) * 512u + (uint32_t)t * 16u, \
                          adj + (size_t)(bq) * LL + t * 4);                     \
        cp_commit();                                                            \
    } while (0)

    SMX_ISSUE(bx, 0);

    for (int i = 0; i < 4; i++) {
        const int bq = i * 256 + bx;
        const int bf = i & 1;
        const int b  = bq >> 7, q = bq & 127;

        if (i < 3) { SMX_ISSUE((i + 1) * 256 + bx, bf ^ 1); cp_wait<1>(); }
        else       { cp_wait<0>(); }
        __syncthreads();

        // transpose dG row -> gT[j][h]
        #pragma unroll
        for (int i0 = 0; i0 < 2; i0++) {
            int ii = t + i0 * 256;
            int h = ii >> 6, j = ii & 63;
            gT[j * 8 + h] = gRaw[bf * 512 + ii];
        }
        __syncthreads();

        const float* esb = es + bf * 8192;
        const int k  = t & 127;
        const int jh = t >> 7;

        // ---- phase A: partial dots (swizzled es) ----
        ull acc2[4] = {0, 0, 0, 0};
        #pragma unroll
        for (int j4 = 0; j4 < 8; j4++) {
            int c4 = jh * 8 + j4;
            int p  = c4 ^ (k & 15);
            float4 ev4 = *(const float4*)(esb + k * 64 + p * 4);
            float evv[4] = {ev4.x, ev4.y, ev4.z, ev4.w};
            #pragma unroll
            for (int c = 0; c < 4; c++) {
                int j = c4 * 4 + c;
                ull ed = pack2(evv[c], evv[c]);
                ulonglong2 g01 = *(const ulonglong2*)(gT + j * 8);
                ulonglong2 g23 = *(const ulonglong2*)(gT + j * 8 + 4);
                fma2(acc2[0], ed, g01.x); fma2(acc2[1], ed, g01.y);
                fma2(acc2[2], ed, g23.x); fma2(acc2[3], ed, g23.y);
            }
        }
        if (jh == 1) {
            *(ulonglong2*)(aT + k * 8)     = make_ulonglong2(acc2[0], acc2[1]);
            *(ulonglong2*)(aT + k * 8 + 4) = make_ulonglong2(acc2[2], acc2[3]);
        }
        __syncthreads();

        // ---- phase B: exp + sum ----
        float p8[8];
        if (t < 128) {
            float sv[8];
            ulonglong2 p01 = *(const ulonglong2*)(aT + k * 8);
            ulonglong2 p23 = *(const ulonglong2*)(aT + k * 8 + 4);
            add2(acc2[0], p01.x); add2(acc2[1], p01.y);
            add2(acc2[2], p23.x); add2(acc2[3], p23.y);
            unpack2(acc2[0], sv[0], sv[1]);
            unpack2(acc2[1], sv[2], sv[3]);
            unpack2(acc2[2], sv[4], sv[5]);
            unpack2(acc2[3], sv[6], sv[7]);
            const int adjv = adjs[bf * 128 + k];
            #pragma unroll
            for (int h = 0; h < HH; h++) {
                float s = (sS1[bf * 1024 + h * 128 + k] + sv[h]) * 0.125f;
                s = (s > 0.f) ? s : 0.2f * s;
                p8[h] = (adjv == 0) ? 0.f : __expf(s);
            }
            #pragma unroll
            for (int h = 0; h < HH; h++) {
                float s = p8[h];
                #pragma unroll
                for (int o = 16; o > 0; o >>= 1) s += __shfl_xor_sync(0xffffffffu, s, o);
                if (lane == 0) redS[warp * 8 + h] = s;
            }
        }
        __syncthreads();

        if (t < 128) {
            float al[8];
            #pragma unroll
            for (int h = 0; h < HH; h++) {
                float tot = redS[h] + redS[8 + h] + redS[16 + h] + redS[24 + h];
                al[h] = __fdividef(p8[h], tot);
                dALPHA[(((size_t)(b * HH + h)) * LL + q) * LL + k] = al[h];
            }
            *(float4*)(aT + k * 8)     = make_float4(al[0], al[1], al[2], al[3]);
            *(float4*)(aT + k * 8 + 4) = make_float4(al[4], al[5], al[6], al[7]);
        }
        __syncthreads();

        // ---- phase C: Wsum (swizzled scalar es reads, conflict-free) ----
        const int ei = t & 63, qt = t >> 6;
        ull w2[4] = {0, 0, 0, 0};
        #pragma unroll 8
        for (int kk = 0; kk < 32; kk++) {
            int kq = qt * 32 + kk;
            int pw = (((ei >> 2) ^ (kq & 15)) << 2) + (ei & 3);
            float ev = esb[kq * 64 + pw];
            ull ed = pack2(ev, ev);
            ulonglong2 a01 = *(const ulonglong2*)(aT + kq * 8);
            ulonglong2 a23 = *(const ulonglong2*)(aT + kq * 8 + 4);
            fma2(w2[0], ed, a01.x); fma2(w2[1], ed, a01.y);
            fma2(w2[2], ed, a23.x); fma2(w2[3], ed, a23.y);
        }
        __syncthreads();

        if (qt == 1) {
            *(ulonglong2*)(aT + ei * 8)     = make_ulonglong2(w2[0], w2[1]);
            *(ulonglong2*)(aT + ei * 8 + 4) = make_ulonglong2(w2[2], w2[3]);
        } else if (qt == 2) {
            *(ulonglong2*)(aT + 512 + ei * 8)     = make_ulonglong2(w2[0], w2[1]);
            *(ulonglong2*)(aT + 512 + ei * 8 + 4) = make_ulonglong2(w2[2], w2[3]);
        } else if (qt == 3) {
            *(ulonglong2*)(gT + ei * 8)     = make_ulonglong2(w2[0], w2[1]);
            *(ulonglong2*)(gT + ei * 8 + 4) = make_ulonglong2(w2[2], w2[3]);
        }
        __syncthreads();

        if (qt == 0) {
            ulonglong2 s1a = *(const ulonglong2*)(aT + ei * 8);
            ulonglong2 s1b = *(const ulonglong2*)(aT + ei * 8 + 4);
            ulonglong2 s2a = *(const ulonglong2*)(aT + 512 + ei * 8);
            ulonglong2 s2b = *(const ulonglong2*)(aT + 512 + ei * 8 + 4);
            ulonglong2 s3a = *(const ulonglong2*)(gT + ei * 8);
            ulonglong2 s3b = *(const ulonglong2*)(gT + ei * 8 + 4);
            add2(w2[0], s1a.x); add2(w2[1], s1a.y); add2(w2[2], s1b.x); add2(w2[3], s1b.y);
            add2(w2[0], s2a.x); add2(w2[1], s2a.y); add2(w2[2], s2b.x); add2(w2[3], s2b.y);
            add2(w2[0], s3a.x); add2(w2[1], s3a.y); add2(w2[2], s3b.x); add2(w2[3], s3b.y);
            float w[8];
            unpack2(w2[0], w[0], w[1]); unpack2(w2[1], w[2], w[3]);
            unpack2(w2[2], w[4], w[5]); unpack2(w2[3], w[6], w[7]);
            #pragma unroll
            for (int h = 0; h < HH; h++)
                dWsum[(((size_t)(b * HH + h)) * LL + q) * EE + ei] = w[h];
        }
        __syncthreads();   // all buffer/gT/aT reads done before next iter's reuse
    }
    #undef SMX_ISSUE
}

// ---------------------------------------------------------------------------
// LayerNorm + ReLU per row of 512
// ---------------------------------------------------------------------------
__global__ __launch_bounds__(256) void ln_kernel(
    const float* __restrict__ gamma, const float* __restrict__ beta,
    float* __restrict__ out)
{
    const int r = blockIdx.x;
    const int t = threadIdx.x;
    const int lane = t & 31, warp = t >> 5;

    float v0 = dFFN_P[(size_t)r * DD + t];
    float v1 = dFFN_P[(size_t)r * DD + 256 + t];
    float s  = v0 + v1;
    float sq = v0 * v0 + v1 * v1;

    __shared__ float rs[8], rq[8];
    __shared__ float mu_s, rstd_s;
    #pragma unroll
    for (int o = 16; o > 0; o >>= 1) {
        s  += __shfl_xor_sync(0xffffffffu, s, o);
        sq += __shfl_xor_sync(0xffffffffu, sq, o);
    }
    if (lane == 0) { rs[warp] = s; rq[warp] = sq; }
    __syncthreads();
    if (t == 0) {
        float S = 0.f, Q2 = 0.f;
        #pragma unroll
        for (int w = 0; w < 8; w++) { S += rs[w]; Q2 += rq[w]; }
        float mu  = S / 512.f;
        float var = Q2 / 512.f - mu * mu;
        mu_s = mu;
        rstd_s = rsqrtf(var + 1e-5f);
    }
    __syncthreads();
    float mu = mu_s, rstd = rstd_s;

    float y0 = (v0 - mu) * rstd * gamma[t]       + beta[t];
    float y1 = (v1 - mu) * rstd * gamma[256 + t] + beta[256 + t];
    out[(size_t)r * DD + t]       = fmaxf(y0, 0.f);
    out[(size_t)r * DD + 256 + t] = fmaxf(y1, 0.f);
}

// ---------------------------------------------------------------------------
extern "C" void kernel_launch(void* const* d_in, const int* in_sizes, int n_in,
                              void* d_out, int out_size)
{
    const float* x     = (const float*)d_in[0];
    const int*   adj   = (const int*)  d_in[1];
    const float* e     = (const float*)d_in[2];
    const float* Wq    = (const float*)d_in[3];
    const float* Wkv   = (const float*)d_in[4];
    const float* We    = (const float*)d_in[5];
    const float* Wf    = (const float*)d_in[6];
    const float* bf    = (const float*)d_in[7];
    const float* gamma = (const float*)d_in[8];
    const float* beta  = (const float*)d_in[9];
    float* out = (float*)d_out;

    static int attr_set = 0;
    if (!attr_set) {
        cudaFuncSetAttribute(softmax7, cudaFuncAttributeMaxDynamicSharedMemorySize, 85120);
        attr_set = 1;
    }

    float* pACC;
    cudaGetSymbolAddress((void**)&pACC, dACC);
    float* pQ    = pACC;
    float* pKV   = pACC + (size_t)BL * DD;
    float* pATTN = pACC + (size_t)2 * BL * DD;
    float* pFFN  = pACC + (size_t)3 * BL * DD;

    // 0. single memset for all split-K accumulation targets
    cudaMemsetAsync(pACC, 0, (size_t)4 * BL * DD * sizeof(float));

    // 1. Q = x@Wq, KV = x@Wkv  (split-K 2: 512 CTAs)
    gemm_ca<<<dim3(DD/64, BL/64, 4), 128>>>(x, Wq, pQ, Wkv, pKV, nullptr,
                                            DD, DD/2, DD, 2);
    // 2+3. S1 and g merged
    s1g_kernel<<<256, 256>>>(We);
    // 4. softmax (persistent, double-buffered streams)
    softmax7<<<256, 256, 85120>>>(e, adj);
    // 5. attention output (split-K 2, 128 threads — R12 best)
    attn_ca<<<dim3(BB*HH, 2, 2), 128>>>(We);
    // 6. FFN GEMM with bias (split-K 2)
    gemm_ca<<<dim3(DD/64, BL/64, 2), 128>>>(pATTN, Wf, pFFN, nullptr, nullptr, bf,
                                            DD, DD/2, DD, 2);
    // 7. LayerNorm + ReLU
    ln_kernel<<<BL, 256>>>(gamma, beta, out);
}

// round 15
// speedup vs baseline: 1.0393x; 1.0393x over previous
#include <cuda_runtime.h>
#include <math.h>
#include <stdint.h>

#define BB 8
#define LL 128
#define DD 512
#define EE 64
#define HH 8
#define BL (BB*LL)   // 1024

typedef unsigned long long ull;

__device__ __forceinline__ void fma2(ull &acc, ull a, ull b) {
    asm("fma.rn.f32x2 %0, %1, %2, %0;" : "+l"(acc) : "l"(a), "l"(b));
}
__device__ __forceinline__ void add2(ull &a, ull b) {
    asm("add.rn.f32x2 %0, %0, %1;" : "+l"(a) : "l"(b));
}
__device__ __forceinline__ ull pack2(float x, float y) {
    ull r; asm("mov.b64 %0, {%1,%2};" : "=l"(r) : "f"(x), "f"(y)); return r;
}
__device__ __forceinline__ void unpack2(ull v, float &x, float &y) {
    asm("mov.b64 {%0,%1}, %2;" : "=f"(x), "=f"(y) : "l"(v));
}
__device__ __forceinline__ float fsum2(ull v) {
    float x, y; unpack2(v, x, y); return x + y;
}

// cp.async helpers
__device__ __forceinline__ uint32_t smem_u32(const void* p) {
    uint32_t a;
    asm("{ .reg .u64 t; cvta.to.shared.u64 t, %1; cvt.u32.u64 %0, t; }" : "=r"(a) : "l"(p));
    return a;
}
__device__ __forceinline__ void cp16(uint32_t d, const void* s) {
    asm volatile("cp.async.ca.shared.global [%0], [%1], 16;" :: "r"(d), "l"(s));
}
__device__ __forceinline__ void cp_commit() {
    asm volatile("cp.async.commit_group;" ::: "memory");
}
template<int N> __device__ __forceinline__ void cp_wait() {
    asm volatile("cp.async.wait_group %0;" :: "n"(N) : "memory");
}

// Scratch — split-K accumulation targets in ONE array (single memset node)
__device__ float dACC[4 * BL * DD];      // [dQ | dKV | dATTN | dFFN]
#define dQ_P    (dACC)
#define dKV_P   (dACC + (size_t)BL * DD)
#define dATTN_P (dACC + (size_t)2 * BL * DD)
#define dFFN_P  (dACC + (size_t)3 * BL * DD)

__device__ float dG[BL*HH*EE];           // [bq][h][e]
__device__ float dS1[BB*HH*LL*LL];       // [bh][q][k]
__device__ float dALPHA[BB*HH*LL*LL];    // [bh][q][k]
__device__ float dWsum[BB*HH*LL*EE];     // [bh][q][e]

// ---------------------------------------------------------------------------
// Split-K cp.async f32x2 GEMM: 64x64 tile, 128 threads, 2-stage (R12 proven).
// ---------------------------------------------------------------------------
__global__ __launch_bounds__(128) void gemm_ca(
    const float* __restrict__ A,
    const float* __restrict__ B0, float* __restrict__ C0,
    const float* __restrict__ B1, float* __restrict__ C1,
    const float* __restrict__ bias, int lda, int K2, int N, int nsplit)
{
    __shared__ float As[2][64*36];
    __shared__ float Bs[2][32*64];

    const int mat = blockIdx.z / nsplit;
    const int sp  = blockIdx.z % nsplit;
    const float* Bm = mat ? B1 : B0;
    float*       Cm = mat ? C1 : C0;
    const int kbase = sp * K2;

    const int t  = threadIdx.x;
    const int tx = t & 15, ty = t >> 4;
    const int m0 = blockIdx.y * 64, n0 = blockIdx.x * 64;

    const uint32_t asb = smem_u32(&As[0][0]);
    const uint32_t bsb = smem_u32(&Bs[0][0]);

    ull acc[8][2] = {};

    #define ISSUE_TILE(buf, k0) do {                                            \
        _Pragma("unroll")                                                       \
        for (int r = 0; r < 4; r++) {                                           \
            int idx = t + r * 128;                                              \
            int m = idx >> 3, k4 = (idx & 7) << 2;                              \
            cp16(asb + (buf) * 9216u + (uint32_t)(m * 36 + k4) * 4u,            \
                 A + (size_t)(m0 + m) * lda + (k0) + k4);                       \
        }                                                                       \
        _Pragma("unroll")                                                       \
        for (int r = 0; r < 4; r++) {                                           \
            int idx = t + r * 128;                                              \
            int kk = idx >> 4, n4 = (idx & 15) << 2;                            \
            cp16(bsb + (buf) * 8192u + (uint32_t)(kk * 64 + n4) * 4u,           \
                 Bm + (size_t)((k0) + kk) * N + n0 + n4);                       \
        }                                                                       \
        cp_commit();                                                            \
    } while (0)

    ISSUE_TILE(0, kbase);

    const int NT = K2 / 32;
    int buf = 0;
    for (int kt = 0; kt < NT; kt++) {
        if (kt + 1 < NT) { ISSUE_TILE(buf ^ 1, kbase + (kt + 1) * 32); cp_wait<1>(); }
        else             { cp_wait<0>(); }
        __syncthreads();

        #pragma unroll 4
        for (int kk = 0; kk < 32; kk += 2) {
            ull bp00 = *(const ull*)&Bs[buf][kk * 64 + tx * 2];
            ull bp01 = *(const ull*)&Bs[buf][kk * 64 + tx * 2 + 32];
            ull bp10 = *(const ull*)&Bs[buf][(kk + 1) * 64 + tx * 2];
            ull bp11 = *(const ull*)&Bs[buf][(kk + 1) * 64 + tx * 2 + 32];
            #pragma unroll
            for (int i = 0; i < 8; i++) {
                float2 af = *(const float2*)&As[buf][(ty * 8 + i) * 36 + kk];
                ull ad0 = pack2(af.x, af.x);
                ull ad1 = pack2(af.y, af.y);
                fma2(acc[i][0], ad0, bp00);
                fma2(acc[i][1], ad0, bp01);
                fma2(acc[i][0], ad1, bp10);
                fma2(acc[i][1], ad1, bp11);
            }
        }
        __syncthreads();
        buf ^= 1;
    }
    #undef ISSUE_TILE

    #pragma unroll
    for (int i = 0; i < 8; i++) {
        int m = m0 + ty * 8 + i;
        float x0, x1, y0, y1;
        unpack2(acc[i][0], x0, x1);
        unpack2(acc[i][1], y0, y1);
        int nA = n0 + tx * 2, nB = nA + 32;
        if (bias && sp == 0) {
            x0 += bias[nA]; x1 += bias[nA + 1];
            y0 += bias[nB]; y1 += bias[nB + 1];
        }
        float* crow = Cm + (size_t)m * N;
        atomicAdd(crow + nA,     x0);
        atomicAdd(crow + nA + 1, x1);
        atomicAdd(crow + nB,     y0);
        atomicAdd(crow + nB + 1, y1);
    }
}

// ---------------------------------------------------------------------------
// attn split-K cp.async GEMM (R12/R14 measured best): 64x64 tiles, 128 threads,
// grid (64, 2, 2); K=192 -> 2x96. atomicAdd into zeroed dATTN.
// ---------------------------------------------------------------------------
__global__ __launch_bounds__(128) void attn_ca(const float* __restrict__ We)
{
    __shared__ float As[2][64*36];
    __shared__ float Bs[2][32*64];

    const int bh = blockIdx.x, mh = blockIdx.y, sp = blockIdx.z;
    const int b  = bh >> 3, h = bh & 7;
    const int t  = threadIdx.x;
    const int tx = t & 15, ty = t >> 4;
    const int kbase = sp * 96;

    const uint32_t asb = smem_u32(&As[0][0]);
    const uint32_t bsb = smem_u32(&Bs[0][0]);

    ull acc[8][2] = {};

    #define ISSUE_ATTN(buf, k0) do {                                            \
        _Pragma("unroll")                                                       \
        for (int r = 0; r < 4; r++) {                                           \
            int idx = t + r * 128;                                              \
            int m = idx >> 3, k4 = (idx & 7) << 2;                              \
            size_t row = (size_t)bh * LL + mh * 64 + m;                         \
            const float* src = ((k0) < 128)                                     \
                ? (dALPHA + row * LL + (k0) + k4)                               \
                : (dWsum  + row * EE + ((k0) - 128) + k4);                      \
            cp16(asb + (buf) * 9216u + (uint32_t)(m * 36 + k4) * 4u, src);      \
        }                                                                       \
        _Pragma("unroll")                                                       \
        for (int r = 0; r < 4; r++) {                                           \
            int idx = t + r * 128;                                              \
            int kk = idx >> 4, n4 = (idx & 15) << 2;                            \
            int kg = (k0) + kk;                                                 \
            const float* src = (kg < 128)                                       \
                ? (dKV_P + (size_t)(b * LL + kg) * DD + h * 64 + n4)            \
                : (We    + (size_t)(kg - 128) * DD + h * 64 + n4);              \
            cp16(bsb + (buf) * 8192u + (uint32_t)(kk * 64 + n4) * 4u, src);     \
        }                                                                       \
        cp_commit();                                                            \
    } while (0)

    ISSUE_ATTN(0, kbase);

    const int NT = 3;   // 96 per split
    int buf = 0;
    for (int kt = 0; kt < NT; kt++) {
        if (kt + 1 < NT) { ISSUE_ATTN(buf ^ 1, kbase + (kt + 1) * 32); cp_wait<1>(); }
        else             { cp_wait<0>(); }
        __syncthreads();

        #pragma unroll 4
        for (int kk = 0; kk < 32; kk += 2) {
            ull bp00 = *(const ull*)&Bs[buf][kk * 64 + tx * 2];
            ull bp01 = *(const ull*)&Bs[buf][kk * 64 + tx * 2 + 32];
            ull bp10 = *(const ull*)&Bs[buf][(kk + 1) * 64 + tx * 2];
            ull bp11 = *(const ull*)&Bs[buf][(kk + 1) * 64 + tx * 2 + 32];
            #pragma unroll
            for (int i = 0; i < 8; i++) {
                float2 af = *(const float2*)&As[buf][(ty * 8 + i) * 36 + kk];
                ull ad0 = pack2(af.x, af.x);
                ull ad1 = pack2(af.y, af.y);
                fma2(acc[i][0], ad0, bp00);
                fma2(acc[i][1], ad0, bp01);
                fma2(acc[i][0], ad1, bp10);
                fma2(acc[i][1], ad1, bp11);
            }
        }
        __syncthreads();
        buf ^= 1;
    }
    #undef ISSUE_ATTN

    #pragma unroll
    for (int i = 0; i < 8; i++) {
        int m = mh * 64 + ty * 8 + i;
        float* crow = dATTN_P + ((size_t)(b * LL) + m) * DD + h * 64;
        float x0, x1, y0, y1;
        unpack2(acc[i][0], x0, x1);
        unpack2(acc[i][1], y0, y1);
        atomicAdd(crow + tx * 2,      x0);
        atomicAdd(crow + tx * 2 + 1,  x1);
        atomicAdd(crow + tx * 2 + 32, y0);
        atomicAdd(crow + tx * 2 + 33, y1);
    }
}

// ---------------------------------------------------------------------------
// Merged s1 + g kernel (proven): 256 blocks x 256 threads.
// ---------------------------------------------------------------------------
__global__ __launch_bounds__(256) void s1g_kernel(const float* __restrict__ We)
{
    __shared__ float pool[8320];

    const int bx = blockIdx.x;
    const int t  = threadIdx.x;
    const int tx = t & 15, ty = t >> 4;

    if (bx < 128) {
        float* Qs = pool;            // [64][34]
        float* Ks = pool + 2176;     // [128][34]
        const int bh = bx >> 1, mh = bx & 1;
        const int b  = bh >> 3, h = bh & 7;

        ull acc[4][8] = {};

        for (int c0 = 0; c0 < 64; c0 += 32) {
            #pragma unroll
            for (int r = 0; r < 2; r++) {
                int idx = t + r * 256;
                int m   = idx >> 3;
                int c4  = (idx & 7) << 2;
                float4 v = *(const float4*)(dQ_P + (size_t)(b * LL + mh * 64 + m) * DD + h * 64 + c0 + c4);
                *(float2*)(Qs + m * 34 + c4)     = make_float2(v.x, v.y);
                *(float2*)(Qs + m * 34 + c4 + 2) = make_float2(v.z, v.w);
            }
            #pragma unroll
            for (int r = 0; r < 4; r++) {
                int idx = t + r * 256;
                int n   = idx >> 3;
                int c4  = (idx & 7) << 2;
                float4 v = *(const float4*)(dKV_P + (size_t)(b * LL + n) * DD + h * 64 + c0 + c4);
                *(float2*)(Ks + n * 34 + c4)     = make_float2(v.x, v.y);
                *(float2*)(Ks + n * 34 + c4 + 2) = make_float2(v.z, v.w);
            }
            __syncthreads();

            #pragma unroll
            for (int cc = 0; cc < 32; cc += 2) {
                ull a[4], b2[8];
                #pragma unroll
                for (int i = 0; i < 4; i++) a[i]  = *(const ull*)(Qs + (ty * 4 + i) * 34 + cc);
                #pragma unroll
                for (int j = 0; j < 8; j++) b2[j] = *(const ull*)(Ks + (tx + 16 * j) * 34 + cc);
                #pragma unroll
                for (int i = 0; i < 4; i++)
                    #pragma unroll
                    for (int j = 0; j < 8; j++)
                        fma2(acc[i][j], a[i], b2[j]);
            }
            __syncthreads();
        }

        #pragma unroll
        for (int i = 0; i < 4; i++) {
            int m = mh * 64 + ty * 4 + i;
            #pragma unroll
            for (int j = 0; j < 8; j++)
                dS1[((size_t)bh * LL + m) * LL + tx + 16 * j] = fsum2(acc[i][j]);
        }
    } else {
        float* Qs = pool;            // [64][65]
        float* Ws = pool + 4160;     // [64][65]
        const int idx0 = bx - 128;
        const int r0 = (idx0 >> 3) * 64;
        const int h  = idx0 & 7;

        #pragma unroll
        for (int r = 0; r < 4; r++) {
            int idx = t + r * 256;
            int m   = idx >> 4;
            int c4  = (idx & 15) << 2;
            float4 q = *(const float4*)(dQ_P + (size_t)(r0 + m) * DD + h * 64 + c4);
            Qs[m * 65 + c4 + 0] = q.x; Qs[m * 65 + c4 + 1] = q.y;
            Qs[m * 65 + c4 + 2] = q.z; Qs[m * 65 + c4 + 3] = q.w;
            float4 w = *(const float4*)(We + (size_t)m * DD + h * 64 + c4);
            Ws[m * 65 + c4 + 0] = w.x; Ws[m * 65 + c4 + 1] = w.y;
            Ws[m * 65 + c4 + 2] = w.z; Ws[m * 65 + c4 + 3] = w.w;
        }
        __syncthreads();

        float acc[4][4] = {};
        #pragma unroll
        for (int c = 0; c < 64; c++) {
            float a[4], b[4];
            #pragma unroll
            for (int i = 0; i < 4; i++) a[i] = Qs[(ty + 16 * i) * 65 + c];
            #pragma unroll
            for (int j = 0; j < 4; j++) b[j] = Ws[(tx + 16 * j) * 65 + c];
            #pragma unroll
            for (int i = 0; i < 4; i++)
                #pragma unroll
                for (int j = 0; j < 4; j++)
                    acc[i][j] += a[i] * b[j];
        }

        #pragma unroll
        for (int i = 0; i < 4; i++) {
            int m = r0 + ty + 16 * i;
            #pragma unroll
            for (int j = 0; j < 4; j++)
                dG[((size_t)m * HH + h) * EE + tx + 16 * j] = acc[i][j];
        }
    }
}

// ---------------------------------------------------------------------------
// Softmax v6s: R13-proven softmax6 structure (static smem, 5 blocks/SM,
// occupancy-pipelined) + XOR-swizzled es layout validated in R14:
//   store: float4 col p = c4 ^ (k & 15), row stride 64 (no pad).
//   Phase A row reads: 2-way instead of 4-way bank conflicts.
//   Phase C column reads: conflict-free (scalar pw formula).
// smem 43.1 KB.
// ---------------------------------------------------------------------------
__global__ __launch_bounds__(256, 5) void softmax6s(
    const float* __restrict__ eptr, const int* __restrict__ adj)
{
    __shared__ float es[128 * 64];   // 32 KB, swizzled
    __shared__ float sS1[8 * 128];   // 4 KB  [h][k]
    __shared__ float gT[512];        // [j][h]; reused for wsum q3 partials
    __shared__ float aT[1024];       // dot partials / alpha / wsum q1,q2 partials
    __shared__ float redS[32];

    const int bq = blockIdx.x;
    const int b  = bq >> 7, q = bq & 127;
    const int t  = threadIdx.x;
    const int lane = t & 31, warp = t >> 5;

    const uint32_t esb = smem_u32(es);
    const uint32_t s1b = smem_u32(sS1);

    // stream es (swizzled) + dS1 slab via cp.async
    const float* erow = eptr + (size_t)bq * LL * EE;
    #pragma unroll
    for (int r = 0; r < 8; r++) {
        int idx = t + r * 256;
        int k   = idx >> 4;
        int c4  = idx & 15;
        int p   = c4 ^ (k & 15);
        cp16(esb + (uint32_t)(k * 256 + p * 16), erow + k * EE + c4 * 4);
    }
    {
        int h  = t >> 5;
        int k4 = (t & 31) << 2;
        cp16(s1b + (uint32_t)(h * 128 + k4) * 4u,
             dS1 + (((size_t)(b * HH + h)) * LL + q) * LL + k4);
    }
    cp_commit();

    // overlapped: gT transpose + adj load
    #pragma unroll
    for (int i0 = 0; i0 < 2; i0++) {
        int i = t + i0 * 256;
        int h = i >> 6, j = i & 63;
        gT[j * 8 + h] = dG[(size_t)bq * 512 + i];
    }
    const int k  = t & 127;
    const int jh = t >> 7;
    int adjv = 1;
    if (t < 128) adjv = adj[(size_t)bq * LL + k];

    cp_wait<0>();
    __syncthreads();

    // ---- phase A: partial dots (swizzled es rows) ----
    ull acc2[4] = {0, 0, 0, 0};
    #pragma unroll
    for (int j4 = 0; j4 < 8; j4++) {
        int c4 = jh * 8 + j4;
        int p  = c4 ^ (k & 15);
        float4 ev4 = *(const float4*)(es + k * 64 + p * 4);
        float evv[4] = {ev4.x, ev4.y, ev4.z, ev4.w};
        #pragma unroll
        for (int c = 0; c < 4; c++) {
            int j = c4 * 4 + c;
            ull ed = pack2(evv[c], evv[c]);
            ulonglong2 g01 = *(const ulonglong2*)(gT + j * 8);
            ulonglong2 g23 = *(const ulonglong2*)(gT + j * 8 + 4);
            fma2(acc2[0], ed, g01.x); fma2(acc2[1], ed, g01.y);
            fma2(acc2[2], ed, g23.x); fma2(acc2[3], ed, g23.y);
        }
    }
    if (jh == 1) {
        *(ulonglong2*)(aT + k * 8)     = make_ulonglong2(acc2[0], acc2[1]);
        *(ulonglong2*)(aT + k * 8 + 4) = make_ulonglong2(acc2[2], acc2[3]);
    }
    __syncthreads();

    // ---- phase B: exp + sum (no max pass; scores bounded) ----
    float p8[8];
    if (t < 128) {
        float sv[8];
        ulonglong2 p01 = *(const ulonglong2*)(aT + k * 8);
        ulonglong2 p23 = *(const ulonglong2*)(aT + k * 8 + 4);
        add2(acc2[0], p01.x); add2(acc2[1], p01.y);
        add2(acc2[2], p23.x); add2(acc2[3], p23.y);
        unpack2(acc2[0], sv[0], sv[1]);
        unpack2(acc2[1], sv[2], sv[3]);
        unpack2(acc2[2], sv[4], sv[5]);
        unpack2(acc2[3], sv[6], sv[7]);
        #pragma unroll
        for (int h = 0; h < HH; h++) {
            float s = (sS1[h * 128 + k] + sv[h]) * 0.125f;
            s = (s > 0.f) ? s : 0.2f * s;
            p8[h] = (adjv == 0) ? 0.f : __expf(s);
        }
        #pragma unroll
        for (int h = 0; h < HH; h++) {
            float s = p8[h];
            #pragma unroll
            for (int o = 16; o > 0; o >>= 1) s += __shfl_xor_sync(0xffffffffu, s, o);
            if (lane == 0) redS[warp * 8 + h] = s;
        }
    }
    __syncthreads();

    if (t < 128) {
        float al[8];
        #pragma unroll
        for (int h = 0; h < HH; h++) {
            float tot = redS[h] + redS[8 + h] + redS[16 + h] + redS[24 + h];
            al[h] = __fdividef(p8[h], tot);
            dALPHA[(((size_t)(b * HH + h)) * LL + q) * LL + k] = al[h];
        }
        *(float4*)(aT + k * 8)     = make_float4(al[0], al[1], al[2], al[3]);
        *(float4*)(aT + k * 8 + 4) = make_float4(al[4], al[5], al[6], al[7]);
    }
    __syncthreads();

    // ---- phase C: Wsum (swizzled scalar es reads, conflict-free) ----
    const int ei = t & 63, qt = t >> 6;
    ull w2[4] = {0, 0, 0, 0};
    #pragma unroll 8
    for (int kk = 0; kk < 32; kk++) {
        int kq = qt * 32 + kk;
        int pw = (((ei >> 2) ^ (kq & 15)) << 2) + (ei & 3);
        float ev = es[kq * 64 + pw];
        ull ed = pack2(ev, ev);
        ulonglong2 a01 = *(const ulonglong2*)(aT + kq * 8);
        ulonglong2 a23 = *(const ulonglong2*)(aT + kq * 8 + 4);
        fma2(w2[0], ed, a01.x); fma2(w2[1], ed, a01.y);
        fma2(w2[2], ed, a23.x); fma2(w2[3], ed, a23.y);
    }
    __syncthreads();

    if (qt == 1) {
        *(ulonglong2*)(aT + ei * 8)     = make_ulonglong2(w2[0], w2[1]);
        *(ulonglong2*)(aT + ei * 8 + 4) = make_ulonglong2(w2[2], w2[3]);
    } else if (qt == 2) {
        *(ulonglong2*)(aT + 512 + ei * 8)     = make_ulonglong2(w2[0], w2[1]);
        *(ulonglong2*)(aT + 512 + ei * 8 + 4) = make_ulonglong2(w2[2], w2[3]);
    } else if (qt == 3) {
        *(ulonglong2*)(gT + ei * 8)     = make_ulonglong2(w2[0], w2[1]);
        *(ulonglong2*)(gT + ei * 8 + 4) = make_ulonglong2(w2[2], w2[3]);
    }
    __syncthreads();

    if (qt == 0) {
        ulonglong2 s1a = *(const ulonglong2*)(aT + ei * 8);
        ulonglong2 s1b2 = *(const ulonglong2*)(aT + ei * 8 + 4);
        ulonglong2 s2a = *(const ulonglong2*)(aT + 512 + ei * 8);
        ulonglong2 s2b = *(const ulonglong2*)(aT + 512 + ei * 8 + 4);
        ulonglong2 s3a = *(const ulonglong2*)(gT + ei * 8);
        ulonglong2 s3b = *(const ulonglong2*)(gT + ei * 8 + 4);
        add2(w2[0], s1a.x); add2(w2[1], s1a.y); add2(w2[2], s1b2.x); add2(w2[3], s1b2.y);
        add2(w2[0], s2a.x); add2(w2[1], s2a.y); add2(w2[2], s2b.x);  add2(w2[3], s2b.y);
        add2(w2[0], s3a.x); add2(w2[1], s3a.y); add2(w2[2], s3b.x);  add2(w2[3], s3b.y);
        float w[8];
        unpack2(w2[0], w[0], w[1]); unpack2(w2[1], w[2], w[3]);
        unpack2(w2[2], w[4], w[5]); unpack2(w2[3], w[6], w[7]);
        #pragma unroll
        for (int h = 0; h < HH; h++)
            dWsum[(((size_t)(b * HH + h)) * LL + q) * EE + ei] = w[h];
    }
}

// ---------------------------------------------------------------------------
// LayerNorm + ReLU per row of 512
// ---------------------------------------------------------------------------
__global__ __launch_bounds__(256) void ln_kernel(
    const float* __restrict__ gamma, const float* __restrict__ beta,
    float* __restrict__ out)
{
    const int r = blockIdx.x;
    const int t = threadIdx.x;
    const int lane = t & 31, warp = t >> 5;

    float v0 = dFFN_P[(size_t)r * DD + t];
    float v1 = dFFN_P[(size_t)r * DD + 256 + t];
    float s  = v0 + v1;
    float sq = v0 * v0 + v1 * v1;

    __shared__ float rs[8], rq[8];
    __shared__ float mu_s, rstd_s;
    #pragma unroll
    for (int o = 16; o > 0; o >>= 1) {
        s  += __shfl_xor_sync(0xffffffffu, s, o);
        sq += __shfl_xor_sync(0xffffffffu, sq, o);
    }
    if (lane == 0) { rs[warp] = s; rq[warp] = sq; }
    __syncthreads();
    if (t == 0) {
        float S = 0.f, Q2 = 0.f;
        #pragma unroll
        for (int w = 0; w < 8; w++) { S += rs[w]; Q2 += rq[w]; }
        float mu  = S / 512.f;
        float var = Q2 / 512.f - mu * mu;
        mu_s = mu;
        rstd_s = rsqrtf(var + 1e-5f);
    }
    __syncthreads();
    float mu = mu_s, rstd = rstd_s;

    float y0 = (v0 - mu) * rstd * gamma[t]       + beta[t];
    float y1 = (v1 - mu) * rstd * gamma[256 + t] + beta[256 + t];
    out[(size_t)r * DD + t]       = fmaxf(y0, 0.f);
    out[(size_t)r * DD + 256 + t] = fmaxf(y1, 0.f);
}

// ---------------------------------------------------------------------------
extern "C" void kernel_launch(void* const* d_in, const int* in_sizes, int n_in,
                              void* d_out, int out_size)
{
    const float* x     = (const float*)d_in[0];
    const int*   adj   = (const int*)  d_in[1];
    const float* e     = (const float*)d_in[2];
    const float* Wq    = (const float*)d_in[3];
    const float* Wkv   = (const float*)d_in[4];
    const float* We    = (const float*)d_in[5];
    const float* Wf    = (const float*)d_in[6];
    const float* bf    = (const float*)d_in[7];
    const float* gamma = (const float*)d_in[8];
    const float* beta  = (const float*)d_in[9];
    float* out = (float*)d_out;

    float* pACC;
    cudaGetSymbolAddress((void**)&pACC, dACC);
    float* pQ    = pACC;
    float* pKV   = pACC + (size_t)BL * DD;
    float* pATTN = pACC + (size_t)2 * BL * DD;
    float* pFFN  = pACC + (size_t)3 * BL * DD;

    // 0. single memset for all split-K accumulation targets
    cudaMemsetAsync(pACC, 0, (size_t)4 * BL * DD * sizeof(float));

    // 1. Q = x@Wq, KV = x@Wkv  (split-K 2: 512 CTAs)
    gemm_ca<<<dim3(DD/64, BL/64, 4), 128>>>(x, Wq, pQ, Wkv, pKV, nullptr,
                                            DD, DD/2, DD, 2);
    // 2+3. S1 and g merged
    s1g_kernel<<<256, 256>>>(We);
    // 4. softmax (swizzled es, occupancy-pipelined)
    softmax6s<<<BL, 256>>>(e, adj);
    // 5. attention output (split-K 2, 128 threads)
    attn_ca<<<dim3(BB*HH, 2, 2), 128>>>(We);
    // 6. FFN GEMM with bias (split-K 2)
    gemm_ca<<<dim3(DD/64, BL/64, 2), 128>>>(pATTN, Wf, pFFN, nullptr, nullptr, bf,
                                            DD, DD/2, DD, 2);
    // 7. LayerNorm + ReLU
    ln_kernel<<<BL, 256>>>(gamma, beta, out);
}

// round 16
// speedup vs baseline: 1.0443x; 1.0048x over previous
#include <cuda_runtime.h>
#include <math.h>
#include <stdint.h>

#define BB 8
#define LL 128
#define DD 512
#define EE 64
#define HH 8
#define BL (BB*LL)   // 1024

typedef unsigned long long ull;

__device__ __forceinline__ void fma2(ull &acc, ull a, ull b) {
    asm("fma.rn.f32x2 %0, %1, %2, %0;" : "+l"(acc) : "l"(a), "l"(b));
}
__device__ __forceinline__ void add2(ull &a, ull b) {
    asm("add.rn.f32x2 %0, %0, %1;" : "+l"(a) : "l"(b));
}
__device__ __forceinline__ ull pack2(float x, float y) {
    ull r; asm("mov.b64 %0, {%1,%2};" : "=l"(r) : "f"(x), "f"(y)); return r;
}
__device__ __forceinline__ void unpack2(ull v, float &x, float &y) {
    asm("mov.b64 {%0,%1}, %2;" : "=f"(x), "=f"(y) : "l"(v));
}
__device__ __forceinline__ float fsum2(ull v) {
    float x, y; unpack2(v, x, y); return x + y;
}
// vectorized global reduction (sm_90+): one 16B red instead of 4 scalar REDs
__device__ __forceinline__ void red4(float* p, float a, float b, float c, float d) {
    asm volatile("red.global.add.v4.f32 [%0], {%1, %2, %3, %4};"
                 :: "l"(p), "f"(a), "f"(b), "f"(c), "f"(d) : "memory");
}

// cp.async helpers
__device__ __forceinline__ uint32_t smem_u32(const void* p) {
    uint32_t a;
    asm("{ .reg .u64 t; cvta.to.shared.u64 t, %1; cvt.u32.u64 %0, t; }" : "=r"(a) : "l"(p));
    return a;
}
__device__ __forceinline__ void cp16(uint32_t d, const void* s) {
    asm volatile("cp.async.ca.shared.global [%0], [%1], 16;" :: "r"(d), "l"(s));
}
__device__ __forceinline__ void cp_commit() {
    asm volatile("cp.async.commit_group;" ::: "memory");
}
template<int N> __device__ __forceinline__ void cp_wait() {
    asm volatile("cp.async.wait_group %0;" :: "n"(N) : "memory");
}

// Scratch — split-K accumulation targets in ONE array (single memset node)
__device__ float dACC[4 * BL * DD];      // [dQ | dKV | dATTN | dFFN]
#define dQ_P    (dACC)
#define dKV_P   (dACC + (size_t)BL * DD)
#define dATTN_P (dACC + (size_t)2 * BL * DD)
#define dFFN_P  (dACC + (size_t)3 * BL * DD)

__device__ float dG[BL*HH*EE];           // [bq][h][e]
__device__ float dS1[BB*HH*LL*LL];       // [bh][q][k]
__device__ float dALPHA[BB*HH*LL*LL];    // [bh][q][k]
__device__ float dWsum[BB*HH*LL*EE];     // [bh][q][e]

// ---------------------------------------------------------------------------
// Split-K cp.async f32x2 GEMM: 64x64 tile, 128 threads, 2-stage.
// Fragment: n-QUADS (tx*4..tx*4+3) -> epilogue is 8 red.v4 per thread.
// ---------------------------------------------------------------------------
__global__ __launch_bounds__(128) void gemm_ca(
    const float* __restrict__ A,
    const float* __restrict__ B0, float* __restrict__ C0,
    const float* __restrict__ B1, float* __restrict__ C1,
    const float* __restrict__ bias, int lda, int K2, int N, int nsplit)
{
    __shared__ float As[2][64*36];
    __shared__ float Bs[2][32*64];

    const int mat = blockIdx.z / nsplit;
    const int sp  = blockIdx.z % nsplit;
    const float* Bm = mat ? B1 : B0;
    float*       Cm = mat ? C1 : C0;
    const int kbase = sp * K2;

    const int t  = threadIdx.x;
    const int tx = t & 15, ty = t >> 4;
    const int m0 = blockIdx.y * 64, n0 = blockIdx.x * 64;

    const uint32_t asb = smem_u32(&As[0][0]);
    const uint32_t bsb = smem_u32(&Bs[0][0]);

    ull acc[8][2] = {};   // acc[i][0]=(n4,n4+1), acc[i][1]=(n4+2,n4+3), n4 = tx*4

    #define ISSUE_TILE(buf, k0) do {                                            \
        _Pragma("unroll")                                                       \
        for (int r = 0; r < 4; r++) {                                           \
            int idx = t + r * 128;                                              \
            int m = idx >> 3, k4 = (idx & 7) << 2;                              \
            cp16(asb + (buf) * 9216u + (uint32_t)(m * 36 + k4) * 4u,            \
                 A + (size_t)(m0 + m) * lda + (k0) + k4);                       \
        }                                                                       \
        _Pragma("unroll")                                                       \
        for (int r = 0; r < 4; r++) {                                           \
            int idx = t + r * 128;                                              \
            int kk = idx >> 4, n4 = (idx & 15) << 2;                            \
            cp16(bsb + (buf) * 8192u + (uint32_t)(kk * 64 + n4) * 4u,           \
                 Bm + (size_t)((k0) + kk) * N + n0 + n4);                       \
        }                                                                       \
        cp_commit();                                                            \
    } while (0)

    ISSUE_TILE(0, kbase);

    const int NT = K2 / 32;
    int buf = 0;
    for (int kt = 0; kt < NT; kt++) {
        if (kt + 1 < NT) { ISSUE_TILE(buf ^ 1, kbase + (kt + 1) * 32); cp_wait<1>(); }
        else             { cp_wait<0>(); }
        __syncthreads();

        #pragma unroll 4
        for (int kk = 0; kk < 32; kk += 2) {
            float4 b0 = *(const float4*)&Bs[buf][kk * 64 + tx * 4];
            float4 b1 = *(const float4*)&Bs[buf][(kk + 1) * 64 + tx * 4];
            ull b0lo = pack2(b0.x, b0.y), b0hi = pack2(b0.z, b0.w);
            ull b1lo = pack2(b1.x, b1.y), b1hi = pack2(b1.z, b1.w);
            #pragma unroll
            for (int i = 0; i < 8; i++) {
                float2 af = *(const float2*)&As[buf][(ty * 8 + i) * 36 + kk];
                ull ad0 = pack2(af.x, af.x);
                ull ad1 = pack2(af.y, af.y);
                fma2(acc[i][0], ad0, b0lo);
                fma2(acc[i][1], ad0, b0hi);
                fma2(acc[i][0], ad1, b1lo);
                fma2(acc[i][1], ad1, b1hi);
            }
        }
        __syncthreads();
        buf ^= 1;
    }
    #undef ISSUE_TILE

    const int n4 = n0 + tx * 4;
    #pragma unroll
    for (int i = 0; i < 8; i++) {
        int m = m0 + ty * 8 + i;
        float r0, r1, r2, r3;
        unpack2(acc[i][0], r0, r1);
        unpack2(acc[i][1], r2, r3);
        if (bias && sp == 0) {
            r0 += bias[n4];     r1 += bias[n4 + 1];
            r2 += bias[n4 + 2]; r3 += bias[n4 + 3];
        }
        red4(Cm + (size_t)m * N + n4, r0, r1, r2, r3);
    }
}

// ---------------------------------------------------------------------------
// attn split-K cp.async GEMM: 64x64 tiles, 128 threads, grid (64, 2, 2);
// K=192 -> 2x96. Quad fragments + red.v4 epilogue into zeroed dATTN.
// ---------------------------------------------------------------------------
__global__ __launch_bounds__(128) void attn_ca(const float* __restrict__ We)
{
    __shared__ float As[2][64*36];
    __shared__ float Bs[2][32*64];

    const int bh = blockIdx.x, mh = blockIdx.y, sp = blockIdx.z;
    const int b  = bh >> 3, h = bh & 7;
    const int t  = threadIdx.x;
    const int tx = t & 15, ty = t >> 4;
    const int kbase = sp * 96;

    const uint32_t asb = smem_u32(&As[0][0]);
    const uint32_t bsb = smem_u32(&Bs[0][0]);

    ull acc[8][2] = {};

    #define ISSUE_ATTN(buf, k0) do {                                            \
        _Pragma("unroll")                                                       \
        for (int r = 0; r < 4; r++) {                                           \
            int idx = t + r * 128;                                              \
            int m = idx >> 3, k4 = (idx & 7) << 2;                              \
            size_t row = (size_t)bh * LL + mh * 64 + m;                         \
            const float* src = ((k0) < 128)                                     \
                ? (dALPHA + row * LL + (k0) + k4)                               \
                : (dWsum  + row * EE + ((k0) - 128) + k4);                      \
            cp16(asb + (buf) * 9216u + (uint32_t)(m * 36 + k4) * 4u, src);      \
        }                                                                       \
        _Pragma("unroll")                                                       \
        for (int r = 0; r < 4; r++) {                                           \
            int idx = t + r * 128;                                              \
            int kk = idx >> 4, n4 = (idx & 15) << 2;                            \
            int kg = (k0) + kk;                                                 \
            const float* src = (kg < 128)                                       \
                ? (dKV_P + (size_t)(b * LL + kg) * DD + h * 64 + n4)            \
                : (We    + (size_t)(kg - 128) * DD + h * 64 + n4);              \
            cp16(bsb + (buf) * 8192u + (uint32_t)(kk * 64 + n4) * 4u, src);     \
        }                                                                       \
        cp_commit();                                                            \
    } while (0)

    ISSUE_ATTN(0, kbase);

    const int NT = 3;   // 96 per split
    int buf = 0;
    for (int kt = 0; kt < NT; kt++) {
        if (kt + 1 < NT) { ISSUE_ATTN(buf ^ 1, kbase + (kt + 1) * 32); cp_wait<1>(); }
        else             { cp_wait<0>(); }
        __syncthreads();

        #pragma unroll 4
        for (int kk = 0; kk < 32; kk += 2) {
            float4 b0 = *(const float4*)&Bs[buf][kk * 64 + tx * 4];
            float4 b1 = *(const float4*)&Bs[buf][(kk + 1) * 64 + tx * 4];
            ull b0lo = pack2(b0.x, b0.y), b0hi = pack2(b0.z, b0.w);
            ull b1lo = pack2(b1.x, b1.y), b1hi = pack2(b1.z, b1.w);
            #pragma unroll
            for (int i = 0; i < 8; i++) {
                float2 af = *(const float2*)&As[buf][(ty * 8 + i) * 36 + kk];
                ull ad0 = pack2(af.x, af.x);
                ull ad1 = pack2(af.y, af.y);
                fma2(acc[i][0], ad0, b0lo);
                fma2(acc[i][1], ad0, b0hi);
                fma2(acc[i][0], ad1, b1lo);
                fma2(acc[i][1], ad1, b1hi);
            }
        }
        __syncthreads();
        buf ^= 1;
    }
    #undef ISSUE_ATTN

    #pragma unroll
    for (int i = 0; i < 8; i++) {
        int m = mh * 64 + ty * 8 + i;
        float* crow = dATTN_P + ((size_t)(b * LL) + m) * DD + h * 64;
        float r0, r1, r2, r3;
        unpack2(acc[i][0], r0, r1);
        unpack2(acc[i][1], r2, r3);
        red4(crow + tx * 4, r0, r1, r2, r3);
    }
}

// ---------------------------------------------------------------------------
// Merged s1 + g kernel (proven): 256 blocks x 256 threads.
// ---------------------------------------------------------------------------
__global__ __launch_bounds__(256) void s1g_kernel(const float* __restrict__ We)
{
    __shared__ float pool[8320];

    const int bx = blockIdx.x;
    const int t  = threadIdx.x;
    const int tx = t & 15, ty = t >> 4;

    if (bx < 128) {
        float* Qs = pool;            // [64][34]
        float* Ks = pool + 2176;     // [128][34]
        const int bh = bx >> 1, mh = bx & 1;
        const int b  = bh >> 3, h = bh & 7;

        ull acc[4][8] = {};

        for (int c0 = 0; c0 < 64; c0 += 32) {
            #pragma unroll
            for (int r = 0; r < 2; r++) {
                int idx = t + r * 256;
                int m   = idx >> 3;
                int c4  = (idx & 7) << 2;
                float4 v = *(const float4*)(dQ_P + (size_t)(b * LL + mh * 64 + m) * DD + h * 64 + c0 + c4);
                *(float2*)(Qs + m * 34 + c4)     = make_float2(v.x, v.y);
                *(float2*)(Qs + m * 34 + c4 + 2) = make_float2(v.z, v.w);
            }
            #pragma unroll
            for (int r = 0; r < 4; r++) {
                int idx = t + r * 256;
                int n   = idx >> 3;
                int c4  = (idx & 7) << 2;
                float4 v = *(const float4*)(dKV_P + (size_t)(b * LL + n) * DD + h * 64 + c0 + c4);
                *(float2*)(Ks + n * 34 + c4)     = make_float2(v.x, v.y);
                *(float2*)(Ks + n * 34 + c4 + 2) = make_float2(v.z, v.w);
            }
            __syncthreads();

            #pragma unroll
            for (int cc = 0; cc < 32; cc += 2) {
                ull a[4], b2[8];
                #pragma unroll
                for (int i = 0; i < 4; i++) a[i]  = *(const ull*)(Qs + (ty * 4 + i) * 34 + cc);
                #pragma unroll
                for (int j = 0; j < 8; j++) b2[j] = *(const ull*)(Ks + (tx + 16 * j) * 34 + cc);
                #pragma unroll
                for (int i = 0; i < 4; i++)
                    #pragma unroll
                    for (int j = 0; j < 8; j++)
                        fma2(acc[i][j], a[i], b2[j]);
            }
            __syncthreads();
        }

        #pragma unroll
        for (int i = 0; i < 4; i++) {
            int m = mh * 64 + ty * 4 + i;
            #pragma unroll
            for (int j = 0; j < 8; j++)
                dS1[((size_t)bh * LL + m) * LL + tx + 16 * j] = fsum2(acc[i][j]);
        }
    } else {
        float* Qs = pool;            // [64][65]
        float* Ws = pool + 4160;     // [64][65]
        const int idx0 = bx - 128;
        const int r0 = (idx0 >> 3) * 64;
        const int h  = idx0 & 7;

        #pragma unroll
        for (int r = 0; r < 4; r++) {
            int idx = t + r * 256;
            int m   = idx >> 4;
            int c4  = (idx & 15) << 2;
            float4 q = *(const float4*)(dQ_P + (size_t)(r0 + m) * DD + h * 64 + c4);
            Qs[m * 65 + c4 + 0] = q.x; Qs[m * 65 + c4 + 1] = q.y;
            Qs[m * 65 + c4 + 2] = q.z; Qs[m * 65 + c4 + 3] = q.w;
            float4 w = *(const float4*)(We + (size_t)m * DD + h * 64 + c4);
            Ws[m * 65 + c4 + 0] = w.x; Ws[m * 65 + c4 + 1] = w.y;
            Ws[m * 65 + c4 + 2] = w.z; Ws[m * 65 + c4 + 3] = w.w;
        }
        __syncthreads();

        float acc[4][4] = {};
        #pragma unroll
        for (int c = 0; c < 64; c++) {
            float a[4], b[4];
            #pragma unroll
            for (int i = 0; i < 4; i++) a[i] = Qs[(ty + 16 * i) * 65 + c];
            #pragma unroll
            for (int j = 0; j < 4; j++) b[j] = Ws[(tx + 16 * j) * 65 + c];
            #pragma unroll
            for (int i = 0; i < 4; i++)
                #pragma unroll
                for (int j = 0; j < 4; j++)
                    acc[i][j] += a[i] * b[j];
        }

        #pragma unroll
        for (int i = 0; i < 4; i++) {
            int m = r0 + ty + 16 * i;
            #pragma unroll
            for (int j = 0; j < 4; j++)
                dG[((size_t)m * HH + h) * EE + tx + 16 * j] = acc[i][j];
        }
    }
}

// ---------------------------------------------------------------------------
// Softmax v6s (R15 proven): swizzled es, 5 blocks/SM, occupancy-pipelined.
// ---------------------------------------------------------------------------
__global__ __launch_bounds__(256, 5) void softmax6s(
    const float* __restrict__ eptr, const int* __restrict__ adj)
{
    __shared__ float es[128 * 64];   // 32 KB, swizzled
    __shared__ float sS1[8 * 128];   // 4 KB  [h][k]
    __shared__ float gT[512];
    __shared__ float aT[1024];
    __shared__ float redS[32];

    const int bq = blockIdx.x;
    const int b  = bq >> 7, q = bq & 127;
    const int t  = threadIdx.x;
    const int lane = t & 31, warp = t >> 5;

    const uint32_t esb = smem_u32(es);
    const uint32_t s1b = smem_u32(sS1);

    const float* erow = eptr + (size_t)bq * LL * EE;
    #pragma unroll
    for (int r = 0; r < 8; r++) {
        int idx = t + r * 256;
        int k   = idx >> 4;
        int c4  = idx & 15;
        int p   = c4 ^ (k & 15);
        cp16(esb + (uint32_t)(k * 256 + p * 16), erow + k * EE + c4 * 4);
    }
    {
        int h  = t >> 5;
        int k4 = (t & 31) << 2;
        cp16(s1b + (uint32_t)(h * 128 + k4) * 4u,
             dS1 + (((size_t)(b * HH + h)) * LL + q) * LL + k4);
    }
    cp_commit();

    #pragma unroll
    for (int i0 = 0; i0 < 2; i0++) {
        int i = t + i0 * 256;
        int h = i >> 6, j = i & 63;
        gT[j * 8 + h] = dG[(size_t)bq * 512 + i];
    }
    const int k  = t & 127;
    const int jh = t >> 7;
    int adjv = 1;
    if (t < 128) adjv = adj[(size_t)bq * LL + k];

    cp_wait<0>();
    __syncthreads();

    // ---- phase A: partial dots ----
    ull acc2[4] = {0, 0, 0, 0};
    #pragma unroll
    for (int j4 = 0; j4 < 8; j4++) {
        int c4 = jh * 8 + j4;
        int p  = c4 ^ (k & 15);
        float4 ev4 = *(const float4*)(es + k * 64 + p * 4);
        float evv[4] = {ev4.x, ev4.y, ev4.z, ev4.w};
        #pragma unroll
        for (int c = 0; c < 4; c++) {
            int j = c4 * 4 + c;
            ull ed = pack2(evv[c], evv[c]);
            ulonglong2 g01 = *(const ulonglong2*)(gT + j * 8);
            ulonglong2 g23 = *(const ulonglong2*)(gT + j * 8 + 4);
            fma2(acc2[0], ed, g01.x); fma2(acc2[1], ed, g01.y);
            fma2(acc2[2], ed, g23.x); fma2(acc2[3], ed, g23.y);
        }
    }
    if (jh == 1) {
        *(ulonglong2*)(aT + k * 8)     = make_ulonglong2(acc2[0], acc2[1]);
        *(ulonglong2*)(aT + k * 8 + 4) = make_ulonglong2(acc2[2], acc2[3]);
    }
    __syncthreads();

    // ---- phase B: exp + sum ----
    float p8[8];
    if (t < 128) {
        float sv[8];
        ulonglong2 p01 = *(const ulonglong2*)(aT + k * 8);
        ulonglong2 p23 = *(const ulonglong2*)(aT + k * 8 + 4);
        add2(acc2[0], p01.x); add2(acc2[1], p01.y);
        add2(acc2[2], p23.x); add2(acc2[3], p23.y);
        unpack2(acc2[0], sv[0], sv[1]);
        unpack2(acc2[1], sv[2], sv[3]);
        unpack2(acc2[2], sv[4], sv[5]);
        unpack2(acc2[3], sv[6], sv[7]);
        #pragma unroll
        for (int h = 0; h < HH; h++) {
            float s = (sS1[h * 128 + k] + sv[h]) * 0.125f;
            s = (s > 0.f) ? s : 0.2f * s;
            p8[h] = (adjv == 0) ? 0.f : __expf(s);
        }
        #pragma unroll
        for (int h = 0; h < HH; h++) {
            float s = p8[h];
            #pragma unroll
            for (int o = 16; o > 0; o >>= 1) s += __shfl_xor_sync(0xffffffffu, s, o);
            if (lane == 0) redS[warp * 8 + h] = s;
        }
    }
    __syncthreads();

    if (t < 128) {
        float al[8];
        #pragma unroll
        for (int h = 0; h < HH; h++) {
            float tot = redS[h] + redS[8 + h] + redS[16 + h] + redS[24 + h];
            al[h] = __fdividef(p8[h], tot);
            dALPHA[(((size_t)(b * HH + h)) * LL + q) * LL + k] = al[h];
        }
        *(float4*)(aT + k * 8)     = make_float4(al[0], al[1], al[2], al[3]);
        *(float4*)(aT + k * 8 + 4) = make_float4(al[4], al[5], al[6], al[7]);
    }
    __syncthreads();

    // ---- phase C: Wsum ----
    const int ei = t & 63, qt = t >> 6;
    ull w2[4] = {0, 0, 0, 0};
    #pragma unroll 8
    for (int kk = 0; kk < 32; kk++) {
        int kq = qt * 32 + kk;
        int pw = (((ei >> 2) ^ (kq & 15)) << 2) + (ei & 3);
        float ev = es[kq * 64 + pw];
        ull ed = pack2(ev, ev);
        ulonglong2 a01 = *(const ulonglong2*)(aT + kq * 8);
        ulonglong2 a23 = *(const ulonglong2*)(aT + kq * 8 + 4);
        fma2(w2[0], ed, a01.x); fma2(w2[1], ed, a01.y);
        fma2(w2[2], ed, a23.x); fma2(w2[3], ed, a23.y);
    }
    __syncthreads();

    if (qt == 1) {
        *(ulonglong2*)(aT + ei * 8)     = make_ulonglong2(w2[0], w2[1]);
        *(ulonglong2*)(aT + ei * 8 + 4) = make_ulonglong2(w2[2], w2[3]);
    } else if (qt == 2) {
        *(ulonglong2*)(aT + 512 + ei * 8)     = make_ulonglong2(w2[0], w2[1]);
        *(ulonglong2*)(aT + 512 + ei * 8 + 4) = make_ulonglong2(w2[2], w2[3]);
    } else if (qt == 3) {
        *(ulonglong2*)(gT + ei * 8)     = make_ulonglong2(w2[0], w2[1]);
        *(ulonglong2*)(gT + ei * 8 + 4) = make_ulonglong2(w2[2], w2[3]);
    }
    __syncthreads();

    if (qt == 0) {
        ulonglong2 s1a = *(const ulonglong2*)(aT + ei * 8);
        ulonglong2 s1b2 = *(const ulonglong2*)(aT + ei * 8 + 4);
        ulonglong2 s2a = *(const ulonglong2*)(aT + 512 + ei * 8);
        ulonglong2 s2b = *(const ulonglong2*)(aT + 512 + ei * 8 + 4);
        ulonglong2 s3a = *(const ulonglong2*)(gT + ei * 8);
        ulonglong2 s3b = *(const ulonglong2*)(gT + ei * 8 + 4);
        add2(w2[0], s1a.x); add2(w2[1], s1a.y); add2(w2[2], s1b2.x); add2(w2[3], s1b2.y);
        add2(w2[0], s2a.x); add2(w2[1], s2a.y); add2(w2[2], s2b.x);  add2(w2[3], s2b.y);
        add2(w2[0], s3a.x); add2(w2[1], s3a.y); add2(w2[2], s3b.x);  add2(w2[3], s3b.y);
        float w[8];
        unpack2(w2[0], w[0], w[1]); unpack2(w2[1], w[2], w[3]);
        unpack2(w2[2], w[4], w[5]); unpack2(w2[3], w[6], w[7]);
        #pragma unroll
        for (int h = 0; h < HH; h++)
            dWsum[(((size_t)(b * HH + h)) * LL + q) * EE + ei] = w[h];
    }
}

// ---------------------------------------------------------------------------
// LayerNorm + ReLU per row of 512
// ---------------------------------------------------------------------------
__global__ __launch_bounds__(256) void ln_kernel(
    const float* __restrict__ gamma, const float* __restrict__ beta,
    float* __restrict__ out)
{
    const int r = blockIdx.x;
    const int t = threadIdx.x;
    const int lane = t & 31, warp = t >> 5;

    float v0 = dFFN_P[(size_t)r * DD + t];
    float v1 = dFFN_P[(size_t)r * DD + 256 + t];
    float s  = v0 + v1;
    float sq = v0 * v0 + v1 * v1;

    __shared__ float rs[8], rq[8];
    __shared__ float mu_s, rstd_s;
    #pragma unroll
    for (int o = 16; o > 0; o >>= 1) {
        s  += __shfl_xor_sync(0xffffffffu, s, o);
        sq += __shfl_xor_sync(0xffffffffu, sq, o);
    }
    if (lane == 0) { rs[warp] = s; rq[warp] = sq; }
    __syncthreads();
    if (t == 0) {
        float S = 0.f, Q2 = 0.f;
        #pragma unroll
        for (int w = 0; w < 8; w++) { S += rs[w]; Q2 += rq[w]; }
        float mu  = S / 512.f;
        float var = Q2 / 512.f - mu * mu;
        mu_s = mu;
        rstd_s = rsqrtf(var + 1e-5f);
    }
    __syncthreads();
    float mu = mu_s, rstd = rstd_s;

    float y0 = (v0 - mu) * rstd * gamma[t]       + beta[t];
    float y1 = (v1 - mu) * rstd * gamma[256 + t] + beta[256 + t];
    out[(size_t)r * DD + t]       = fmaxf(y0, 0.f);
    out[(size_t)r * DD + 256 + t] = fmaxf(y1, 0.f);
}

// ---------------------------------------------------------------------------
extern "C" void kernel_launch(void* const* d_in, const int* in_sizes, int n_in,
                              void* d_out, int out_size)
{
    const float* x     = (const float*)d_in[0];
    const int*   adj   = (const int*)  d_in[1];
    const float* e     = (const float*)d_in[2];
    const float* Wq    = (const float*)d_in[3];
    const float* Wkv   = (const float*)d_in[4];
    const float* We    = (const float*)d_in[5];
    const float* Wf    = (const float*)d_in[6];
    const float* bf    = (const float*)d_in[7];
    const float* gamma = (const float*)d_in[8];
    const float* beta  = (const float*)d_in[9];
    float* out = (float*)d_out;

    float* pACC;
    cudaGetSymbolAddress((void**)&pACC, dACC);
    float* pQ    = pACC;
    float* pKV   = pACC + (size_t)BL * DD;
    float* pATTN = pACC + (size_t)2 * BL * DD;
    float* pFFN  = pACC + (size_t)3 * BL * DD;

    // 0. single memset for all split-K accumulation targets
    cudaMemsetAsync(pACC, 0, (size_t)4 * BL * DD * sizeof(float));

    // 1. Q = x@Wq, KV = x@Wkv  (split-K 2: 512 CTAs, red.v4 epilogue)
    gemm_ca<<<dim3(DD/64, BL/64, 4), 128>>>(x, Wq, pQ, Wkv, pKV, nullptr,
                                            DD, DD/2, DD, 2);
    // 2+3. S1 and g merged
    s1g_kernel<<<256, 256>>>(We);
    // 4. softmax (swizzled es)
    softmax6s<<<BL, 256>>>(e, adj);
    // 5. attention output (split-K 2, red.v4 epilogue)
    attn_ca<<<dim3(BB*HH, 2, 2), 128>>>(We);
    // 6. FFN GEMM with bias (split-K 2, red.v4 epilogue)
    gemm_ca<<<dim3(DD/64, BL/64, 2), 128>>>(pATTN, Wf, pFFN, nullptr, nullptr, bf,
                                            DD, DD/2, DD, 2);
    // 7. LayerNorm + ReLU
    ln_kernel<<<BL, 256>>>(gamma, beta, out);
}

// round 17
// speedup vs baseline: 1.2161x; 1.1645x over previous
#include <cuda_runtime.h>
#include <cuda_bf16.h>
#include <math.h>
#include <stdint.h>

#define BB 8
#define LL 128
#define DD 512
#define EE 64
#define HH 8
#define BL (BB*LL)   // 1024

typedef unsigned long long ull;

__device__ __forceinline__ void fma2(ull &acc, ull a, ull b) {
    asm("fma.rn.f32x2 %0, %1, %2, %0;" : "+l"(acc) : "l"(a), "l"(b));
}
__device__ __forceinline__ void add2(ull &a, ull b) {
    asm("add.rn.f32x2 %0, %0, %1;" : "+l"(a) : "l"(b));
}
__device__ __forceinline__ ull pack2(float x, float y) {
    ull r; asm("mov.b64 %0, {%1,%2};" : "=l"(r) : "f"(x), "f"(y)); return r;
}
__device__ __forceinline__ void unpack2(ull v, float &x, float &y) {
    asm("mov.b64 {%0,%1}, %2;" : "=f"(x), "=f"(y) : "l"(v));
}
__device__ __forceinline__ float fsum2(ull v) {
    float x, y; unpack2(v, x, y); return x + y;
}
__device__ __forceinline__ void red4(float* p, float a, float b, float c, float d) {
    asm volatile("red.global.add.v4.f32 [%0], {%1, %2, %3, %4};"
                 :: "l"(p), "f"(a), "f"(b), "f"(c), "f"(d) : "memory");
}

// bf16 tensor-core MMA (sm_80 path — legal on plain sm_103, lowers to HMMA)
__device__ __forceinline__ void mma16816(float* d,
    uint32_t a0, uint32_t a1, uint32_t a2, uint32_t a3, uint32_t b0, uint32_t b1)
{
    asm volatile(
        "mma.sync.aligned.m16n8k16.row.col.f32.bf16.bf16.f32 "
        "{%0,%1,%2,%3}, {%4,%5,%6,%7}, {%8,%9}, {%0,%1,%2,%3};"
        : "+f"(d[0]), "+f"(d[1]), "+f"(d[2]), "+f"(d[3])
        : "r"(a0), "r"(a1), "r"(a2), "r"(a3), "r"(b0), "r"(b1));
}

// cp.async helpers
__device__ __forceinline__ uint32_t smem_u32(const void* p) {
    uint32_t a;
    asm("{ .reg .u64 t; cvta.to.shared.u64 t, %1; cvt.u32.u64 %0, t; }" : "=r"(a) : "l"(p));
    return a;
}
__device__ __forceinline__ void cp16(uint32_t d, const void* s) {
    asm volatile("cp.async.ca.shared.global [%0], [%1], 16;" :: "r"(d), "l"(s));
}
__device__ __forceinline__ void cp_commit() {
    asm volatile("cp.async.commit_group;" ::: "memory");
}
template<int N> __device__ __forceinline__ void cp_wait() {
    asm volatile("cp.async.wait_group %0;" :: "n"(N) : "memory");
}

// ============================ scratch ============================
__device__ float dACC[4 * BL * DD];      // [dQ | dKV | dATTN | dFFN]
#define dQ_P    (dACC)
#define dKV_P   (dACC + (size_t)BL * DD)
#define dATTN_P (dACC + (size_t)2 * BL * DD)
#define dFFN_P  (dACC + (size_t)3 * BL * DD)

__device__ float dG[BL*HH*EE];
__device__ float dS1[BB*HH*LL*LL];
__device__ float dALPHA[BB*HH*LL*LL];
__device__ float dWsum[BB*HH*LL*EE];

// bf16 split operands
__device__ __nv_bfloat16 dXh[BL*DD],  dXl[BL*DD];     // x hi/lo [m][k]
__device__ __nv_bfloat16 dAh[BL*DD],  dAl[BL*DD];     // attn-out hi/lo
__device__ __nv_bfloat16 dWqh[DD*DD], dWql[DD*DD];    // Wq^T [n][k]
__device__ __nv_bfloat16 dWkh[DD*DD], dWkl[DD*DD];
__device__ __nv_bfloat16 dWfh[DD*DD], dWfl[DD*DD];

// ============================ conversions ============================
__device__ __forceinline__ void split_bf(float x, __nv_bfloat16 &h, __nv_bfloat16 &l) {
    h = __float2bfloat16(x);
    l = __float2bfloat16(x - __bfloat162float(h));
}

__global__ __launch_bounds__(256) void conv_hilo(
    const float* __restrict__ in, __nv_bfloat16* __restrict__ oh,
    __nv_bfloat16* __restrict__ ol)
{
    int i = blockIdx.x * 256 + threadIdx.x;           // over float4s
    float4 v = ((const float4*)in)[i];
    __nv_bfloat16 h0, h1, h2, h3, l0, l1, l2, l3;
    split_bf(v.x, h0, l0); split_bf(v.y, h1, l1);
    split_bf(v.z, h2, l2); split_bf(v.w, h3, l3);
    ((__nv_bfloat162*)oh)[2*i]   = __nv_bfloat162(h0, h1);
    ((__nv_bfloat162*)oh)[2*i+1] = __nv_bfloat162(h2, h3);
    ((__nv_bfloat162*)ol)[2*i]   = __nv_bfloat162(l0, l1);
    ((__nv_bfloat162*)ol)[2*i+1] = __nv_bfloat162(l2, l3);
}

// Wt[n][k] = W[k][n], split to bf16 hi/lo. z selects (Wq, Wkv, Wf).
__global__ __launch_bounds__(256) void conv_w_t(
    const float* __restrict__ W0, const float* __restrict__ W1,
    const float* __restrict__ W2)
{
    __shared__ float tile[32][33];
    const int z = blockIdx.z;
    const float* W = (z == 0) ? W0 : (z == 1) ? W1 : W2;
    __nv_bfloat16* oh = (z == 0) ? dWqh : (z == 1) ? dWkh : dWfh;
    __nv_bfloat16* ol = (z == 0) ? dWql : (z == 1) ? dWkl : dWfl;

    const int t = threadIdx.x;
    const int tx = t & 31, ty = t >> 5;               // ty 0..7
    const int n0 = blockIdx.x * 32, k0 = blockIdx.y * 32;

    #pragma unroll
    for (int r = 0; r < 4; r++)
        tile[ty + 8*r][tx] = W[(size_t)(k0 + ty + 8*r) * DD + n0 + tx];
    __syncthreads();
    #pragma unroll
    for (int r = 0; r < 4; r++) {
        int n = ty + 8*r;
        float v = tile[tx][n];                         // W[k0+tx][n0+n]
        __nv_bfloat16 h, l;
        split_bf(v, h, l);
        oh[(size_t)(n0 + n) * DD + k0 + tx] = h;
        ol[(size_t)(n0 + n) * DD + k0 + tx] = l;
    }
}

// ============================ tensor GEMM ============================
// C[m][n] = A @ Wt^T using split-bf16 (3 MMAs). 64x64 tile, 128 threads,
// K-tile 32, double-buffered cp.async. Smem rows stride 40 bf16 (80B,
// 16B-aligned, conflict-free fragment loads). Direct STG epilogue.
// z selects (B0h/B0l -> C0) vs (B1h/B1l -> C1). bias added when given.
__global__ __launch_bounds__(128) void tensor_gemm(
    const __nv_bfloat16* __restrict__ Ah, const __nv_bfloat16* __restrict__ Al,
    const __nv_bfloat16* __restrict__ B0h, const __nv_bfloat16* __restrict__ B0l,
    float* __restrict__ C0,
    const __nv_bfloat16* __restrict__ B1h, const __nv_bfloat16* __restrict__ B1l,
    float* __restrict__ C1,
    const float* __restrict__ bias)
{
    __shared__ __align__(16) uint16_t Ah_s[2][64*40], Al_s[2][64*40];
    __shared__ __align__(16) uint16_t Bh_s[2][64*40], Bl_s[2][64*40];

    const __nv_bfloat16* Bh = blockIdx.z ? B1h : B0h;
    const __nv_bfloat16* Bl = blockIdx.z ? B1l : B0l;
    float* C = blockIdx.z ? C1 : C0;

    const int t = threadIdx.x;
    const int lane = t & 31, wid = t >> 5;
    const int g = lane >> 2, tq = lane & 3;
    const int wm = wid >> 1, wn = wid & 1;
    const int m0 = blockIdx.y * 64, n0 = blockIdx.x * 64;

    const uint32_t ahb = smem_u32(&Ah_s[0][0]);
    const uint32_t alb = smem_u32(&Al_s[0][0]);
    const uint32_t bhb = smem_u32(&Bh_s[0][0]);
    const uint32_t blb = smem_u32(&Bl_s[0][0]);

    float d[2][4][4] = {};

    // per tile: 64 rows x 32 bf16 per operand = 64B/row = 4 chunks of 16B
    #define ISSUE_T(buf, k0) do {                                               \
        _Pragma("unroll")                                                       \
        for (int r = 0; r < 2; r++) {                                           \
            int idx = t + r * 128;                                              \
            int m = idx >> 2, c = idx & 3;                                      \
            uint32_t off = (uint32_t)(buf) * 5120u + (uint32_t)(m * 80 + c * 16); \
            const size_t asrc = (size_t)(m0 + m) * DD + (k0) + c * 8;           \
            const size_t bsrc = (size_t)(n0 + m) * DD + (k0) + c * 8;           \
            cp16(ahb + off, Ah + asrc);                                         \
            cp16(alb + off, Al + asrc);                                         \
            cp16(bhb + off, Bh + bsrc);                                         \
            cp16(blb + off, Bl + bsrc);                                         \
        }                                                                       \
        cp_commit();                                                            \
    } while (0)

    ISSUE_T(0, 0);

    const int NT = DD / 32;   // 16
    int buf = 0;
    for (int kt = 0; kt < NT; kt++) {
        if (kt + 1 < NT) { ISSUE_T(buf ^ 1, (kt + 1) * 32); cp_wait<1>(); }
        else             { cp_wait<0>(); }
        __syncthreads();

        const uint32_t* A32h = (const uint32_t*)&Ah_s[buf][0];   // stride 20 b32
        const uint32_t* A32l = (const uint32_t*)&Al_s[buf][0];
        const uint32_t* B32h = (const uint32_t*)&Bh_s[buf][0];
        const uint32_t* B32l = (const uint32_t*)&Bl_s[buf][0];

        #pragma unroll
        for (int ks = 0; ks < 2; ks++) {
            const int ko = ks * 8 + tq;
            uint32_t ah[2][4], al[2][4], bh[4][2], bl2[4][2];
            #pragma unroll
            for (int mi = 0; mi < 2; mi++) {
                int row = wm * 32 + mi * 16 + g;
                ah[mi][0] = A32h[row * 20 + ko];
                ah[mi][1] = A32h[(row + 8) * 20 + ko];
                ah[mi][2] = A32h[row * 20 + ko + 4];
                ah[mi][3] = A32h[(row + 8) * 20 + ko + 4];
                al[mi][0] = A32l[row * 20 + ko];
                al[mi][1] = A32l[(row + 8) * 20 + ko];
                al[mi][2] = A32l[row * 20 + ko + 4];
                al[mi][3] = A32l[(row + 8) * 20 + ko + 4];
            }
            #pragma unroll
            for (int ni = 0; ni < 4; ni++) {
                int n = wn * 32 + ni * 8 + g;
                bh[ni][0]  = B32h[n * 20 + ko];
                bh[ni][1]  = B32h[n * 20 + ko + 4];
                bl2[ni][0] = B32l[n * 20 + ko];
                bl2[ni][1] = B32l[n * 20 + ko + 4];
            }
            #pragma unroll
            for (int mi = 0; mi < 2; mi++)
                #pragma unroll
                for (int ni = 0; ni < 4; ni++) {
                    mma16816(d[mi][ni], ah[mi][0], ah[mi][1], ah[mi][2], ah[mi][3],
                             bh[ni][0], bh[ni][1]);
                    mma16816(d[mi][ni], ah[mi][0], ah[mi][1], ah[mi][2], ah[mi][3],
                             bl2[ni][0], bl2[ni][1]);
                    mma16816(d[mi][ni], al[mi][0], al[mi][1], al[mi][2], al[mi][3],
                             bh[ni][0], bh[ni][1]);
                }
        }
        __syncthreads();
        buf ^= 1;
    }
    #undef ISSUE_T

    #pragma unroll
    for (int mi = 0; mi < 2; mi++)
        #pragma unroll
        for (int ni = 0; ni < 4; ni++) {
            int row = m0 + wm * 32 + mi * 16 + g;
            int col = n0 + wn * 32 + ni * 8 + 2 * tq;
            float v0 = d[mi][ni][0], v1 = d[mi][ni][1];
            float v2 = d[mi][ni][2], v3 = d[mi][ni][3];
            if (bias) {
                float b0 = bias[col], b1 = bias[col + 1];
                v0 += b0; v1 += b1; v2 += b0; v3 += b1;
            }
            *(float2*)(C + (size_t)row * DD + col)       = make_float2(v0, v1);
            *(float2*)(C + (size_t)(row + 8) * DD + col) = make_float2(v2, v3);
        }
}

// ---------------------------------------------------------------------------
// attn split-K cp.async GEMM (R16 proven): 64x64, 128 thr, grid (64,2,2),
// red.v4 epilogue into zeroed dATTN.
// ---------------------------------------------------------------------------
__global__ __launch_bounds__(128) void attn_ca(const float* __restrict__ We)
{
    __shared__ float As[2][64*36];
    __shared__ float Bs[2][32*64];

    const int bh = blockIdx.x, mh = blockIdx.y, sp = blockIdx.z;
    const int b  = bh >> 3, h = bh & 7;
    const int t  = threadIdx.x;
    const int tx = t & 15, ty = t >> 4;
    const int kbase = sp * 96;

    const uint32_t asb = smem_u32(&As[0][0]);
    const uint32_t bsb = smem_u32(&Bs[0][0]);

    ull acc[8][2] = {};

    #define ISSUE_ATTN(buf, k0) do {                                            \
        _Pragma("unroll")                                                       \
        for (int r = 0; r < 4; r++) {                                           \
            int idx = t + r * 128;                                              \
            int m = idx >> 3, k4 = (idx & 7) << 2;                              \
            size_t row = (size_t)bh * LL + mh * 64 + m;                         \
            const float* src = ((k0) < 128)                                     \
                ? (dALPHA + row * LL + (k0) + k4)                               \
                : (dWsum  + row * EE + ((k0) - 128) + k4);                      \
            cp16(asb + (buf) * 9216u + (uint32_t)(m * 36 + k4) * 4u, src);      \
        }                                                                       \
        _Pragma("unroll")                                                       \
        for (int r = 0; r < 4; r++) {                                           \
            int idx = t + r * 128;                                              \
            int kk = idx >> 4, n4 = (idx & 15) << 2;                            \
            int kg = (k0) + kk;                                                 \
            const float* src = (kg < 128)                                       \
                ? (dKV_P + (size_t)(b * LL + kg) * DD + h * 64 + n4)            \
                : (We    + (size_t)(kg - 128) * DD + h * 64 + n4);              \
            cp16(bsb + (buf) * 8192u + (uint32_t)(kk * 64 + n4) * 4u, src);     \
        }                                                                       \
        cp_commit();                                                            \
    } while (0)

    ISSUE_ATTN(0, kbase);

    const int NT = 3;
    int buf = 0;
    for (int kt = 0; kt < NT; kt++) {
        if (kt + 1 < NT) { ISSUE_ATTN(buf ^ 1, kbase + (kt + 1) * 32); cp_wait<1>(); }
        else             { cp_wait<0>(); }
        __syncthreads();

        #pragma unroll 4
        for (int kk = 0; kk < 32; kk += 2) {
            float4 b0 = *(const float4*)&Bs[buf][kk * 64 + tx * 4];
            float4 b1 = *(const float4*)&Bs[buf][(kk + 1) * 64 + tx * 4];
            ull b0lo = pack2(b0.x, b0.y), b0hi = pack2(b0.z, b0.w);
            ull b1lo = pack2(b1.x, b1.y), b1hi = pack2(b1.z, b1.w);
            #pragma unroll
            for (int i = 0; i < 8; i++) {
                float2 af = *(const float2*)&As[buf][(ty * 8 + i) * 36 + kk];
                ull ad0 = pack2(af.x, af.x);
                ull ad1 = pack2(af.y, af.y);
                fma2(acc[i][0], ad0, b0lo);
                fma2(acc[i][1], ad0, b0hi);
                fma2(acc[i][0], ad1, b1lo);
                fma2(acc[i][1], ad1, b1hi);
            }
        }
        __syncthreads();
        buf ^= 1;
    }
    #undef ISSUE_ATTN

    #pragma unroll
    for (int i = 0; i < 8; i++) {
        int m = mh * 64 + ty * 8 + i;
        float* crow = dATTN_P + ((size_t)(b * LL) + m) * DD + h * 64;
        float r0, r1, r2, r3;
        unpack2(acc[i][0], r0, r1);
        unpack2(acc[i][1], r2, r3);
        red4(crow + tx * 4, r0, r1, r2, r3);
    }
}

// ---------------------------------------------------------------------------
// Merged s1 + g kernel (proven): 256 blocks x 256 threads.
// ---------------------------------------------------------------------------
__global__ __launch_bounds__(256) void s1g_kernel(const float* __restrict__ We)
{
    __shared__ float pool[8320];

    const int bx = blockIdx.x;
    const int t  = threadIdx.x;
    const int tx = t & 15, ty = t >> 4;

    if (bx < 128) {
        float* Qs = pool;
        float* Ks = pool + 2176;
        const int bh = bx >> 1, mh = bx & 1;
        const int b  = bh >> 3, h = bh & 7;

        ull acc[4][8] = {};

        for (int c0 = 0; c0 < 64; c0 += 32) {
            #pragma unroll
            for (int r = 0; r < 2; r++) {
                int idx = t + r * 256;
                int m   = idx >> 3;
                int c4  = (idx & 7) << 2;
                float4 v = *(const float4*)(dQ_P + (size_t)(b * LL + mh * 64 + m) * DD + h * 64 + c0 + c4);
                *(float2*)(Qs + m * 34 + c4)     = make_float2(v.x, v.y);
                *(float2*)(Qs + m * 34 + c4 + 2) = make_float2(v.z, v.w);
            }
            #pragma unroll
            for (int r = 0; r < 4; r++) {
                int idx = t + r * 256;
                int n   = idx >> 3;
                int c4  = (idx & 7) << 2;
                float4 v = *(const float4*)(dKV_P + (size_t)(b * LL + n) * DD + h * 64 + c0 + c4);
                *(float2*)(Ks + n * 34 + c4)     = make_float2(v.x, v.y);
                *(float2*)(Ks + n * 34 + c4 + 2) = make_float2(v.z, v.w);
            }
            __syncthreads();

            #pragma unroll
            for (int cc = 0; cc < 32; cc += 2) {
                ull a[4], b2[8];
                #pragma unroll
                for (int i = 0; i < 4; i++) a[i]  = *(const ull*)(Qs + (ty * 4 + i) * 34 + cc);
                #pragma unroll
                for (int j = 0; j < 8; j++) b2[j] = *(const ull*)(Ks + (tx + 16 * j) * 34 + cc);
                #pragma unroll
                for (int i = 0; i < 4; i++)
                    #pragma unroll
                    for (int j = 0; j < 8; j++)
                        fma2(acc[i][j], a[i], b2[j]);
            }
            __syncthreads();
        }

        #pragma unroll
        for (int i = 0; i < 4; i++) {
            int m = mh * 64 + ty * 4 + i;
            #pragma unroll
            for (int j = 0; j < 8; j++)
                dS1[((size_t)bh * LL + m) * LL + tx + 16 * j] = fsum2(acc[i][j]);
        }
    } else {
        float* Qs = pool;
        float* Ws = pool + 4160;
        const int idx0 = bx - 128;
        const int r0 = (idx0 >> 3) * 64;
        const int h  = idx0 & 7;

        #pragma unroll
        for (int r = 0; r < 4; r++) {
            int idx = t + r * 256;
            int m   = idx >> 4;
            int c4  = (idx & 15) << 2;
            float4 q = *(const float4*)(dQ_P + (size_t)(r0 + m) * DD + h * 64 + c4);
            Qs[m * 65 + c4 + 0] = q.x; Qs[m * 65 + c4 + 1] = q.y;
            Qs[m * 65 + c4 + 2] = q.z; Qs[m * 65 + c4 + 3] = q.w;
            float4 w = *(const float4*)(We + (size_t)m * DD + h * 64 + c4);
            Ws[m * 65 + c4 + 0] = w.x; Ws[m * 65 + c4 + 1] = w.y;
            Ws[m * 65 + c4 + 2] = w.z; Ws[m * 65 + c4 + 3] = w.w;
        }
        __syncthreads();

        float acc[4][4] = {};
        #pragma unroll
        for (int c = 0; c < 64; c++) {
            float a[4], b[4];
            #pragma unroll
            for (int i = 0; i < 4; i++) a[i] = Qs[(ty + 16 * i) * 65 + c];
            #pragma unroll
            for (int j = 0; j < 4; j++) b[j] = Ws[(tx + 16 * j) * 65 + c];
            #pragma unroll
            for (int i = 0; i < 4; i++)
                #pragma unroll
                for (int j = 0; j < 4; j++)
                    acc[i][j] += a[i] * b[j];
        }

        #pragma unroll
        for (int i = 0; i < 4; i++) {
            int m = r0 + ty + 16 * i;
            #pragma unroll
            for (int j = 0; j < 4; j++)
                dG[((size_t)m * HH + h) * EE + tx + 16 * j] = acc[i][j];
        }
    }
}

// ---------------------------------------------------------------------------
// Softmax v6s (R15/R16 proven): swizzled es, 5 blocks/SM.
// ---------------------------------------------------------------------------
__global__ __launch_bounds__(256, 5) void softmax6s(
    const float* __restrict__ eptr, const int* __restrict__ adj)
{
    __shared__ float es[128 * 64];
    __shared__ float sS1[8 * 128];
    __shared__ float gT[512];
    __shared__ float aT[1024];
    __shared__ float redS[32];

    const int bq = blockIdx.x;
    const int b  = bq >> 7, q = bq & 127;
    const int t  = threadIdx.x;
    const int lane = t & 31, warp = t >> 5;

    const uint32_t esb = smem_u32(es);
    const uint32_t s1b = smem_u32(sS1);

    const float* erow = eptr + (size_t)bq * LL * EE;
    #pragma unroll
    for (int r = 0; r < 8; r++) {
        int idx = t + r * 256;
        int k   = idx >> 4;
        int c4  = idx & 15;
        int p   = c4 ^ (k & 15);
        cp16(esb + (uint32_t)(k * 256 + p * 16), erow + k * EE + c4 * 4);
    }
    {
        int h  = t >> 5;
        int k4 = (t & 31) << 2;
        cp16(s1b + (uint32_t)(h * 128 + k4) * 4u,
             dS1 + (((size_t)(b * HH + h)) * LL + q) * LL + k4);
    }
    cp_commit();

    #pragma unroll
    for (int i0 = 0; i0 < 2; i0++) {
        int i = t + i0 * 256;
        int h = i >> 6, j = i & 63;
        gT[j * 8 + h] = dG[(size_t)bq * 512 + i];
    }
    const int k  = t & 127;
    const int jh = t >> 7;
    int adjv = 1;
    if (t < 128) adjv = adj[(size_t)bq * LL + k];

    cp_wait<0>();
    __syncthreads();

    ull acc2[4] = {0, 0, 0, 0};
    #pragma unroll
    for (int j4 = 0; j4 < 8; j4++) {
        int c4 = jh * 8 + j4;
        int p  = c4 ^ (k & 15);
        float4 ev4 = *(const float4*)(es + k * 64 + p * 4);
        float evv[4] = {ev4.x, ev4.y, ev4.z, ev4.w};
        #pragma unroll
        for (int c = 0; c < 4; c++) {
            int j = c4 * 4 + c;
            ull ed = pack2(evv[c], evv[c]);
            ulonglong2 g01 = *(const ulonglong2*)(gT + j * 8);
            ulonglong2 g23 = *(const ulonglong2*)(gT + j * 8 + 4);
            fma2(acc2[0], ed, g01.x); fma2(acc2[1], ed, g01.y);
            fma2(acc2[2], ed, g23.x); fma2(acc2[3], ed, g23.y);
        }
    }
    if (jh == 1) {
        *(ulonglong2*)(aT + k * 8)     = make_ulonglong2(acc2[0], acc2[1]);
        *(ulonglong2*)(aT + k * 8 + 4) = make_ulonglong2(acc2[2], acc2[3]);
    }
    __syncthreads();

    float p8[8];
    if (t < 128) {
        float sv[8];
        ulonglong2 p01 = *(const ulonglong2*)(aT + k * 8);
        ulonglong2 p23 = *(const ulonglong2*)(aT + k * 8 + 4);
        add2(acc2[0], p01.x); add2(acc2[1], p01.y);
        add2(acc2[2], p23.x); add2(acc2[3], p23.y);
        unpack2(acc2[0], sv[0], sv[1]);
        unpack2(acc2[1], sv[2], sv[3]);
        unpack2(acc2[2], sv[4], sv[5]);
        unpack2(acc2[3], sv[6], sv[7]);
        #pragma unroll
        for (int h = 0; h < HH; h++) {
            float s = (sS1[h * 128 + k] + sv[h]) * 0.125f;
            s = (s > 0.f) ? s : 0.2f * s;
            p8[h] = (adjv == 0) ? 0.f : __expf(s);
        }
        #pragma unroll
        for (int h = 0; h < HH; h++) {
            float s = p8[h];
            #pragma unroll
            for (int o = 16; o > 0; o >>= 1) s += __shfl_xor_sync(0xffffffffu, s, o);
            if (lane == 0) redS[warp * 8 + h] = s;
        }
    }
    __syncthreads();

    if (t < 128) {
        float al[8];
        #pragma unroll
        for (int h = 0; h < HH; h++) {
            float tot = redS[h] + redS[8 + h] + redS[16 + h] + redS[24 + h];
            al[h] = __fdividef(p8[h], tot);
            dALPHA[(((size_t)(b * HH + h)) * LL + q) * LL + k] = al[h];
        }
        *(float4*)(aT + k * 8)     = make_float4(al[0], al[1], al[2], al[3]);
        *(float4*)(aT + k * 8 + 4) = make_float4(al[4], al[5], al[6], al[7]);
    }
    __syncthreads();

    const int ei = t & 63, qt = t >> 6;
    ull w2[4] = {0, 0, 0, 0};
    #pragma unroll 8
    for (int kk = 0; kk < 32; kk++) {
        int kq = qt * 32 + kk;
        int pw = (((ei >> 2) ^ (kq & 15)) << 2) + (ei & 3);
        float ev = es[kq * 64 + pw];
        ull ed = pack2(ev, ev);
        ulonglong2 a01 = *(const ulonglong2*)(aT + kq * 8);
        ulonglong2 a23 = *(const ulonglong2*)(aT + kq * 8 + 4);
        fma2(w2[0], ed, a01.x); fma2(w2[1], ed, a01.y);
        fma2(w2[2], ed, a23.x); fma2(w2[3], ed, a23.y);
    }
    __syncthreads();

    if (qt == 1) {
        *(ulonglong2*)(aT + ei * 8)     = make_ulonglong2(w2[0], w2[1]);
        *(ulonglong2*)(aT + ei * 8 + 4) = make_ulonglong2(w2[2], w2[3]);
    } else if (qt == 2) {
        *(ulonglong2*)(aT + 512 + ei * 8)     = make_ulonglong2(w2[0], w2[1]);
        *(ulonglong2*)(aT + 512 + ei * 8 + 4) = make_ulonglong2(w2[2], w2[3]);
    } else if (qt == 3) {
        *(ulonglong2*)(gT + ei * 8)     = make_ulonglong2(w2[0], w2[1]);
        *(ulonglong2*)(gT + ei * 8 + 4) = make_ulonglong2(w2[2], w2[3]);
    }
    __syncthreads();

    if (qt == 0) {
        ulonglong2 s1a = *(const ulonglong2*)(aT + ei * 8);
        ulonglong2 s1b2 = *(const ulonglong2*)(aT + ei * 8 + 4);
        ulonglong2 s2a = *(const ulonglong2*)(aT + 512 + ei * 8);
        ulonglong2 s2b = *(const ulonglong2*)(aT + 512 + ei * 8 + 4);
        ulonglong2 s3a = *(const ulonglong2*)(gT + ei * 8);
        ulonglong2 s3b = *(const ulonglong2*)(gT + ei * 8 + 4);
        add2(w2[0], s1a.x); add2(w2[1], s1a.y); add2(w2[2], s1b2.x); add2(w2[3], s1b2.y);
        add2(w2[0], s2a.x); add2(w2[1], s2a.y); add2(w2[2], s2b.x);  add2(w2[3], s2b.y);
        add2(w2[0], s3a.x); add2(w2[1], s3a.y); add2(w2[2], s3b.x);  add2(w2[3], s3b.y);
        float w[8];
        unpack2(w2[0], w[0], w[1]); unpack2(w2[1], w[2], w[3]);
        unpack2(w2[2], w[4], w[5]); unpack2(w2[3], w[6], w[7]);
        #pragma unroll
        for (int h = 0; h < HH; h++)
            dWsum[(((size_t)(b * HH + h)) * LL + q) * EE + ei] = w[h];
    }
}

// ---------------------------------------------------------------------------
// LayerNorm + ReLU per row of 512
// ---------------------------------------------------------------------------
__global__ __launch_bounds__(256) void ln_kernel(
    const float* __restrict__ gamma, const float* __restrict__ beta,
    float* __restrict__ out)
{
    const int r = blockIdx.x;
    const int t = threadIdx.x;
    const int lane = t & 31, warp = t >> 5;

    float v0 = dFFN_P[(size_t)r * DD + t];
    float v1 = dFFN_P[(size_t)r * DD + 256 + t];
    float s  = v0 + v1;
    float sq = v0 * v0 + v1 * v1;

    __shared__ float rs[8], rq[8];
    __shared__ float mu_s, rstd_s;
    #pragma unroll
    for (int o = 16; o > 0; o >>= 1) {
        s  += __shfl_xor_sync(0xffffffffu, s, o);
        sq += __shfl_xor_sync(0xffffffffu, sq, o);
    }
    if (lane == 0) { rs[warp] = s; rq[warp] = sq; }
    __syncthreads();
    if (t == 0) {
        float S = 0.f, Q2 = 0.f;
        #pragma unroll
        for (int w = 0; w < 8; w++) { S += rs[w]; Q2 += rq[w]; }
        float mu  = S / 512.f;
        float var = Q2 / 512.f - mu * mu;
        mu_s = mu;
        rstd_s = rsqrtf(var + 1e-5f);
    }
    __syncthreads();
    float mu = mu_s, rstd = rstd_s;

    float y0 = (v0 - mu) * rstd * gamma[t]       + beta[t];
    float y1 = (v1 - mu) * rstd * gamma[256 + t] + beta[256 + t];
    out[(size_t)r * DD + t]       = fmaxf(y0, 0.f);
    out[(size_t)r * DD + 256 + t] = fmaxf(y1, 0.f);
}

// ---------------------------------------------------------------------------
extern "C" void kernel_launch(void* const* d_in, const int* in_sizes, int n_in,
                              void* d_out, int out_size)
{
    const float* x     = (const float*)d_in[0];
    const int*   adj   = (const int*)  d_in[1];
    const float* e     = (const float*)d_in[2];
    const float* Wq    = (const float*)d_in[3];
    const float* Wkv   = (const float*)d_in[4];
    const float* We    = (const float*)d_in[5];
    const float* Wf    = (const float*)d_in[6];
    const float* bf    = (const float*)d_in[7];
    const float* gamma = (const float*)d_in[8];
    const float* beta  = (const float*)d_in[9];
    float* out = (float*)d_out;

    float* pACC;
    cudaGetSymbolAddress((void**)&pACC, dACC);
    float* pQ    = pACC;
    float* pKV   = pACC + (size_t)BL * DD;
    float* pATTN = pACC + (size_t)2 * BL * DD;
    float* pFFN  = pACC + (size_t)3 * BL * DD;

    __nv_bfloat16 *pXh, *pXl, *pAh, *pAl;
    __nv_bfloat16 *pWqh, *pWql, *pWkh, *pWkl, *pWfh, *pWfl;
    cudaGetSymbolAddress((void**)&pXh, dXh);
    cudaGetSymbolAddress((void**)&pXl, dXl);
    cudaGetSymbolAddress((void**)&pAh, dAh);
    cudaGetSymbolAddress((void**)&pAl, dAl);
    cudaGetSymbolAddress((void**)&pWqh, dWqh);
    cudaGetSymbolAddress((void**)&pWql, dWql);
    cudaGetSymbolAddress((void**)&pWkh, dWkh);
    cudaGetSymbolAddress((void**)&pWkl, dWkl);
    cudaGetSymbolAddress((void**)&pWfh, dWfh);
    cudaGetSymbolAddress((void**)&pWfl, dWfl);

    // 0. memset only the attn red-accumulation target
    cudaMemsetAsync(pATTN, 0, (size_t)BL * DD * sizeof(float));

    // 1. conversions: x -> bf16 hi/lo; Wq/Wkv/Wf -> transposed bf16 hi/lo
    conv_hilo<<<BL*DD/4/256, 256>>>(x, pXh, pXl);
    conv_w_t<<<dim3(16, 16, 3), 256>>>(Wq, Wkv, Wf);

    // 2. Q = x@Wq, KV = x@Wkv  — tensor-core split-bf16 GEMM (direct STG)
    tensor_gemm<<<dim3(DD/64, BL/64, 2), 128>>>(pXh, pXl,
                                                pWqh, pWql, pQ,
                                                pWkh, pWkl, pKV, nullptr);
    // 3. S1 and g merged
    s1g_kernel<<<256, 256>>>(We);
    // 4. softmax
    softmax6s<<<BL, 256>>>(e, adj);
    // 5. attention output (split-K 2, red.v4)
    attn_ca<<<dim3(BB*HH, 2, 2), 128>>>(We);
    // 6. attn-out -> bf16 hi/lo, then FFN tensor GEMM with bias
    conv_hilo<<<BL*DD/4/256, 256>>>(pATTN, pAh, pAl);
    tensor_gemm<<<dim3(DD/64, BL/64, 1), 128>>>(pAh, pAl,
                                                pWfh, pWfl, pFFN,
                                                nullptr, nullptr, nullptr, bf);
    // 7. LayerNorm + ReLU
    ln_kernel<<<BL, 256>>>(gamma, beta, out);
}